// round 13
// baseline (speedup 1.0000x reference)
#include <cuda_runtime.h>
#include <cuda_fp16.h>
#include <math.h>
#include <stdint.h>

#define S_LEN 2048
#define D_DIM 1024
#define H_NUM 16
#define HD_DIM 64
#define FF_DIM 4096
#define DEPTH 2
#define NSEG 4
#define EPS 1e-6f

// ---------------- scratch (device globals; allocation-free) ----------------
__device__ __half g_h  [S_LEN * D_DIM];          // LN output (half)
__device__ __half g_qkv[S_LEN * 3 * D_DIM];      // qkv projection (half)
__device__ __half g_ao [S_LEN * D_DIM];          // attention output (half)
__device__ __half g_ff [S_LEN * FF_DIM];         // fc1+gelu output (half)
// half weights [K, N] row-major
__device__ __half g_wq[DEPTH * D_DIM * 3 * D_DIM];
__device__ __half g_wp[DEPTH * D_DIM * D_DIM];
__device__ __half g_w1[DEPTH * D_DIM * FF_DIM];
__device__ __half g_w2[DEPTH * FF_DIM * D_DIM];

// ---------------- helpers ----------------
__device__ __forceinline__ void mma_f16(float* d, const uint32_t* a, const uint32_t* b) {
    asm volatile(
        "mma.sync.aligned.m16n8k16.row.col.f32.f16.f16.f32 "
        "{%0,%1,%2,%3}, {%4,%5,%6,%7}, {%8,%9}, {%0,%1,%2,%3};\n"
        : "+f"(d[0]), "+f"(d[1]), "+f"(d[2]), "+f"(d[3])
        : "r"(a[0]), "r"(a[1]), "r"(a[2]), "r"(a[3]), "r"(b[0]), "r"(b[1]));
}
__device__ __forceinline__ void mma_f16_2(float* d,
                                          uint32_t a0, uint32_t a1, uint32_t a2, uint32_t a3,
                                          uint32_t b0, uint32_t b1) {
    asm volatile(
        "mma.sync.aligned.m16n8k16.row.col.f32.f16.f16.f32 "
        "{%0,%1,%2,%3}, {%4,%5,%6,%7}, {%8,%9}, {%0,%1,%2,%3};\n"
        : "+f"(d[0]), "+f"(d[1]), "+f"(d[2]), "+f"(d[3])
        : "r"(a0), "r"(a1), "r"(a2), "r"(a3), "r"(b0), "r"(b1));
}
__device__ __forceinline__ void ldsm_x4(uint32_t* r, const void* p) {
    uint32_t a = (uint32_t)__cvta_generic_to_shared(p);
    asm volatile("ldmatrix.sync.aligned.m8n8.x4.shared.b16 {%0,%1,%2,%3}, [%4];"
                 : "=r"(r[0]), "=r"(r[1]), "=r"(r[2]), "=r"(r[3]) : "r"(a));
}
__device__ __forceinline__ void ldsm_x4_t(uint32_t* r, const void* p) {
    uint32_t a = (uint32_t)__cvta_generic_to_shared(p);
    asm volatile("ldmatrix.sync.aligned.m8n8.x4.trans.shared.b16 {%0,%1,%2,%3}, [%4];"
                 : "=r"(r[0]), "=r"(r[1]), "=r"(r[2]), "=r"(r[3]) : "r"(a));
}
__device__ __forceinline__ void cp16(void* dst, const void* src) {
    uint32_t d = (uint32_t)__cvta_generic_to_shared(dst);
    asm volatile("cp.async.cg.shared.global [%0], [%1], 16;\n" :: "r"(d), "l"(src));
}
__device__ __forceinline__ void cp_commit() {
    asm volatile("cp.async.commit_group;\n");
}
__device__ __forceinline__ uint32_t h2pack(float a, float b) {
    __half2 h = __floats2half2_rn(a, b);
    return *(uint32_t*)&h;
}

// ------------- fused fp32 -> fp16 conversion, 16 elems/thread --------------
__device__ __forceinline__ void cvt16(const float4* s, uint4* d, int j) {
    float4 a = s[4 * j], b = s[4 * j + 1], c = s[4 * j + 2], e = s[4 * j + 3];
    uint4 o0, o1;
    o0.x = h2pack(a.x, a.y); o0.y = h2pack(a.z, a.w);
    o0.z = h2pack(b.x, b.y); o0.w = h2pack(b.z, b.w);
    o1.x = h2pack(c.x, c.y); o1.y = h2pack(c.z, c.w);
    o1.z = h2pack(e.x, e.y); o1.w = h2pack(e.z, e.w);
    d[2 * j] = o0; d[2 * j + 1] = o1;
}
__global__ void f2h_all_kernel(const float* w0, __half* o0, int n0,   // in 16-elem units
                               const float* w1, __half* o1, int n1,
                               const float* w2, __half* o2, int n2,
                               const float* w3, __half* o3, int n3) {
    int i = blockIdx.x * blockDim.x + threadIdx.x;
    if (i < n0) { cvt16((const float4*)w0, (uint4*)o0, i); return; }
    i -= n0;
    if (i < n1) { cvt16((const float4*)w1, (uint4*)o1, i); return; }
    i -= n1;
    if (i < n2) { cvt16((const float4*)w2, (uint4*)o2, i); return; }
    i -= n2;
    if (i < n3) { cvt16((const float4*)w3, (uint4*)o3, i); }
}

// ---------------- LayerNorm: one WARP per row, half output -----------------
__global__ __launch_bounds__(256)
void ln_kernel(const float* __restrict__ x,
               const float* __restrict__ g,
               const float* __restrict__ b,
               __half* __restrict__ out) {
    const int lane = threadIdx.x & 31;
    const int row  = blockIdx.x * 8 + (threadIdx.x >> 5);
    const float* xr = x + (size_t)row * D_DIM;

    float4 v[8];
    float s = 0.f;
    #pragma unroll
    for (int i = 0; i < 8; i++) {
        v[i] = *(const float4*)(xr + i * 128 + lane * 4);
        s += v[i].x + v[i].y + v[i].z + v[i].w;
    }
    #pragma unroll
    for (int o = 16; o > 0; o >>= 1) s += __shfl_xor_sync(0xffffffffu, s, o);
    const float mean = s * (1.f / D_DIM);

    float var = 0.f;
    #pragma unroll
    for (int i = 0; i < 8; i++) {
        float dx = v[i].x - mean, dy = v[i].y - mean;
        float dz = v[i].z - mean, dw = v[i].w - mean;
        var += dx * dx + dy * dy + dz * dz + dw * dw;
    }
    #pragma unroll
    for (int o = 16; o > 0; o >>= 1) var += __shfl_xor_sync(0xffffffffu, var, o);
    const float rstd = rsqrtf(var * (1.f / D_DIM) + EPS);

    __half* orow = out + (size_t)row * D_DIM;
    #pragma unroll
    for (int i = 0; i < 8; i++) {
        const int col = i * 128 + lane * 4;
        float4 gv = *(const float4*)(g + col);
        float4 bv = *(const float4*)(b + col);
        uint2 o;
        o.x = h2pack((v[i].x - mean) * rstd * gv.x + bv.x,
                     (v[i].y - mean) * rstd * gv.y + bv.y);
        o.y = h2pack((v[i].z - mean) * rstd * gv.z + bv.z,
                     (v[i].w - mean) * rstd * gv.w + bv.w);
        *(uint2*)(orow + col) = o;
    }
}

// ---- FP16 GEMM: BMx128 tile (BM=128 or 64), BK=64, 2-stage cp.async ----
// Warp layout: WM = BM/64 warps over M, WN = 8/WM over N; warp tile 64 x 128/WN.
// EPI: 0 = bias (CT out), 1 = bias + exact GELU (half C), 2 = bias+resid (float C)
#define GSMEM_BYTES(BM) ((2 * (BM) * 72 + 2 * 64 * 136) * 2)
template<int EPI, int BM, typename CT>
__global__ __launch_bounds__(256)
void gemm_f16_kernel(const __half* __restrict__ A,
                     const __half* __restrict__ B,
                     const float* __restrict__ bias,
                     const float* __restrict__ resid,
                     CT* __restrict__ C,
                     int M, int N, int K) {
    constexpr int WM = BM / 64;          // 2 or 1
    constexpr int WN = 8 / WM;           // 4 or 8
    constexpr int NW = 128 / WN;         // 32 or 16 cols per warp
    constexpr int NP = NW / 16;          // 2 or 1 B-ldsm per k16
    constexpr int NI = 2 * NP;           // 4 or 2 acc n-frags

    extern __shared__ __half gsm[];
    __half (*As)[BM][72]  = (__half(*)[BM][72])gsm;
    __half (*Bs)[64][136] = (__half(*)[64][136])(gsm + 2 * BM * 72);

    const int tid  = threadIdx.x;
    const int lane = tid & 31;
    const int wid  = tid >> 5;
    const int warp_m = wid / WN;
    const int warp_n = wid % WN;
    const int g = lane >> 2;
    const int t = lane & 3;

    const int bx = blockIdx.x;
    const int by = blockIdx.y;

    const __half* Ag = A + (size_t)by * BM * K;
    const __half* Bg = B + (size_t)bx * 128;

    float acc[4][NI][4];
    #pragma unroll
    for (int mi = 0; mi < 4; mi++)
        #pragma unroll
        for (int ni = 0; ni < NI; ni++)
            #pragma unroll
            for (int e = 0; e < 4; e++) acc[mi][ni][e] = 0.f;

    const int NIT = K >> 6;    // BK = 64

    auto load_stage = [&](int st, int k0) {
        #pragma unroll
        for (int i = 0; i < BM / 32; i++) {
            int id = tid + 256 * i;
            int r = id >> 3, c = (id & 7) * 8;
            cp16(&As[st][r][c], Ag + (size_t)r * K + k0 + c);
        }
        #pragma unroll
        for (int i = 0; i < 4; i++) {
            int id = tid + 256 * i;
            int r = id >> 4, c = (id & 15) * 8;
            cp16(&Bs[st][r][c], Bg + (size_t)(k0 + r) * N + c);
        }
        cp_commit();
    };

    load_stage(0, 0);

    const int a_row = lane & 15;
    const int a_chk = (lane >> 4) * 8;

    #pragma unroll 1
    for (int it = 0; it < NIT; it++) {
        const int buf = it & 1;
        asm volatile("cp.async.wait_group 0;\n");
        __syncthreads();
        if (it + 1 < NIT) load_stage(buf ^ 1, (it + 1) << 6);

        #pragma unroll
        for (int ks = 0; ks < 4; ks++) {
            uint32_t af[4][4], bf[NI][2];
            #pragma unroll
            for (int mi = 0; mi < 4; mi++) {
                int row = warp_m * 64 + mi * 16 + a_row;
                ldsm_x4(af[mi], &As[buf][row][ks * 16 + a_chk]);
            }
            #pragma unroll
            for (int p = 0; p < NP; p++) {
                uint32_t r[4];
                int krow = ks * 16 + a_row;
                int ncol = warp_n * NW + p * 16 + a_chk;
                ldsm_x4_t(r, &Bs[buf][krow][ncol]);
                bf[p * 2][0] = r[0]; bf[p * 2][1] = r[1];
                bf[p * 2 + 1][0] = r[2]; bf[p * 2 + 1][1] = r[3];
            }
            #pragma unroll
            for (int mi = 0; mi < 4; mi++)
                #pragma unroll
                for (int ni = 0; ni < NI; ni++)
                    mma_f16(acc[mi][ni], af[mi], bf[ni]);
        }
    }

    #pragma unroll
    for (int mi = 0; mi < 4; mi++) {
        const int row0 = by * BM + warp_m * 64 + mi * 16 + g;
        #pragma unroll
        for (int ni = 0; ni < NI; ni++) {
            const int col = bx * 128 + warp_n * NW + (ni >> 1) * 16 + (ni & 1) * 8 + 2 * t;
            #pragma unroll
            for (int half_ = 0; half_ < 2; half_++) {
                const int r = row0 + half_ * 8;
                float v0 = acc[mi][ni][half_ * 2]     + bias[col];
                float v1 = acc[mi][ni][half_ * 2 + 1] + bias[col + 1];
                if (EPI == 1) {
                    v0 = 0.5f * v0 * (1.f + erff(v0 * 0.70710678118654752f));
                    v1 = 0.5f * v1 * (1.f + erff(v1 * 0.70710678118654752f));
                } else if (EPI == 2) {
                    const float* rr = resid + (size_t)r * N + col;
                    v0 += rr[0]; v1 += rr[1];
                }
                if (sizeof(CT) == 2) {
                    *(uint32_t*)((__half*)C + (size_t)r * N + col) = h2pack(v0, v1);
                } else {
                    ((float*)C)[(size_t)r * N + col]     = v0;
                    ((float*)C)[(size_t)r * N + col + 1] = v1;
                }
            }
        }
    }
}

// ---------------- RoPE on q and k slices of half qkv ----------------
__global__ void rope_kernel(__half* __restrict__ qkv,
                            const float* __restrict__ cosp,
                            const float* __restrict__ sinp) {
    int idx = blockIdx.x * blockDim.x + threadIdx.x;  // S*H*16
    if (idx >= S_LEN * H_NUM * 16) return;
    const int d2 = (idx & 15) * 2;
    const int h = (idx >> 4) & (H_NUM - 1);
    const int s = idx >> 8;

    const float2 c1 = *(const float2*)(cosp + s * 64 + d2);
    const float2 c2 = *(const float2*)(cosp + s * 64 + d2 + 32);
    const float2 s1 = *(const float2*)(sinp + s * 64 + d2);
    const float2 s2 = *(const float2*)(sinp + s * 64 + d2 + 32);

    __half* base = qkv + (size_t)s * (3 * D_DIM) + h * HD_DIM + d2;
    #pragma unroll
    for (int qk = 0; qk < 2; qk++) {
        __half* p = base + qk * D_DIM;
        float2 a = __half22float2(*(__half2*)p);
        float2 bv = __half22float2(*(__half2*)(p + 32));
        *(uint32_t*)p        = h2pack(a.x * c1.x - bv.x * s1.x,
                                      a.y * c1.y - bv.y * s1.y);
        *(uint32_t*)(p + 32) = h2pack(bv.x * c2.x + a.x * s2.x,
                                      bv.y * c2.y + a.y * s2.y);
    }
}

// ---- fp16 flash attention, double-buffered cp.async K/V chunks ----
__global__ __launch_bounds__(256)
void attn_kernel(const __half* __restrict__ qkv,
                 const int* __restrict__ cu,
                 __half* __restrict__ ao) {
    const int h  = blockIdx.y;
    const int s0 = blockIdx.x * 128;
    const int tid  = threadIdx.x;
    const int lane = tid & 31;
    const int wid  = tid >> 5;
    const int g = lane >> 2;
    const int t = lane & 3;
    const int a_row = lane & 15;
    const int a_chk = (lane >> 4) * 8;

    __shared__ __half Kh[2][32][72];
    __shared__ __half Vh[2][32][72];

    int start = 0, len = S_LEN;
    #pragma unroll
    for (int i = 0; i < NSEG; i++) {
        int a = cu[i], b = cu[i + 1];
        if (s0 >= a && s0 < b) { start = a; len = b - a; }
    }

    const int pr = wid * 16;

    uint32_t qf[4][4];
    {
        const __half* q0 = qkv + (size_t)(s0 + pr + g) * (3 * D_DIM) + h * HD_DIM;
        const __half* q8 = q0 + 8 * (3 * D_DIM);
        #pragma unroll
        for (int dc = 0; dc < 4; dc++) {
            const int c = dc * 16 + 2 * t;
            qf[dc][0] = *(const uint32_t*)(q0 + c);
            qf[dc][1] = *(const uint32_t*)(q8 + c);
            qf[dc][2] = *(const uint32_t*)(q0 + c + 8);
            qf[dc][3] = *(const uint32_t*)(q8 + c + 8);
        }
    }

    float m0 = -3.4e38f, m1 = -3.4e38f, l0 = 0.f, l1 = 0.f;
    float out[8][4];
    #pragma unroll
    for (int n = 0; n < 8; n++)
        #pragma unroll
        for (int e = 0; e < 4; e++) out[n][e] = 0.f;

    const int kr = tid >> 3;
    const int kc8 = (tid & 7) * 8;
    auto load_chunk = [&](int buf, int kb) {
        const __half* base = qkv + (size_t)(kb + kr) * (3 * D_DIM) + h * HD_DIM + kc8;
        cp16(&Kh[buf][kr][kc8], base + D_DIM);
        cp16(&Vh[buf][kr][kc8], base + 2 * D_DIM);
        cp_commit();
    };

    load_chunk(0, start);

    const int nch = len >> 5;
    for (int c = 0; c < nch; c++) {
        const int buf = c & 1;
        asm volatile("cp.async.wait_group 0;\n");
        __syncthreads();
        if (c + 1 < nch) load_chunk(buf ^ 1, start + (c + 1) * 32);

        // S = Q @ K^T
        float sacc[4][4];
        #pragma unroll
        for (int j = 0; j < 4; j++)
            #pragma unroll
            for (int e = 0; e < 4; e++) sacc[j][e] = 0.f;
        #pragma unroll
        for (int dc = 0; dc < 4; dc++) {
            #pragma unroll
            for (int kh = 0; kh < 2; kh++) {
                uint32_t r[4];
                ldsm_x4(r, &Kh[buf][kh * 16 + a_row][dc * 16 + a_chk]);
                mma_f16_2(sacc[kh * 2],     qf[dc][0], qf[dc][1], qf[dc][2], qf[dc][3],
                          r[0], r[2]);
                mma_f16_2(sacc[kh * 2 + 1], qf[dc][0], qf[dc][1], qf[dc][2], qf[dc][3],
                          r[1], r[3]);
            }
        }
        #pragma unroll
        for (int j = 0; j < 4; j++)
            #pragma unroll
            for (int e = 0; e < 4; e++) sacc[j][e] *= 0.125f;

        // online softmax
        float ml0 = -3.4e38f, ml1 = -3.4e38f;
        #pragma unroll
        for (int j = 0; j < 4; j++) {
            ml0 = fmaxf(ml0, fmaxf(sacc[j][0], sacc[j][1]));
            ml1 = fmaxf(ml1, fmaxf(sacc[j][2], sacc[j][3]));
        }
        ml0 = fmaxf(ml0, __shfl_xor_sync(0xffffffffu, ml0, 1));
        ml0 = fmaxf(ml0, __shfl_xor_sync(0xffffffffu, ml0, 2));
        ml1 = fmaxf(ml1, __shfl_xor_sync(0xffffffffu, ml1, 1));
        ml1 = fmaxf(ml1, __shfl_xor_sync(0xffffffffu, ml1, 2));
        const float mn0 = fmaxf(m0, ml0);
        const float mn1 = fmaxf(m1, ml1);
        const float f0 = __expf(m0 - mn0);
        const float f1 = __expf(m1 - mn1);

        uint32_t pa[2][4];
        float ll0 = 0.f, ll1 = 0.f;
        #pragma unroll
        for (int j = 0; j < 4; j++) {
            float p0 = __expf(sacc[j][0] - mn0);
            float p1 = __expf(sacc[j][1] - mn0);
            float p2 = __expf(sacc[j][2] - mn1);
            float p3 = __expf(sacc[j][3] - mn1);
            ll0 += p0 + p1; ll1 += p2 + p3;
            pa[j >> 1][(j & 1) * 2]     = h2pack(p0, p1);
            pa[j >> 1][(j & 1) * 2 + 1] = h2pack(p2, p3);
        }
        ll0 += __shfl_xor_sync(0xffffffffu, ll0, 1);
        ll0 += __shfl_xor_sync(0xffffffffu, ll0, 2);
        ll1 += __shfl_xor_sync(0xffffffffu, ll1, 1);
        ll1 += __shfl_xor_sync(0xffffffffu, ll1, 2);
        l0 = l0 * f0 + ll0;
        l1 = l1 * f1 + ll1;
        m0 = mn0; m1 = mn1;
        #pragma unroll
        for (int n = 0; n < 8; n++) {
            out[n][0] *= f0; out[n][1] *= f0;
            out[n][2] *= f1; out[n][3] *= f1;
        }

        // out += P @ V
        #pragma unroll
        for (int kc = 0; kc < 2; kc++) {
            #pragma unroll
            for (int p = 0; p < 4; p++) {
                uint32_t r[4];
                ldsm_x4_t(r, &Vh[buf][kc * 16 + a_row][p * 16 + a_chk]);
                mma_f16(out[p * 2], pa[kc], r);
                mma_f16_2(out[p * 2 + 1], pa[kc][0], pa[kc][1], pa[kc][2], pa[kc][3],
                          r[2], r[3]);
            }
        }
    }

    const float i0 = 1.f / l0;
    const float i1 = 1.f / l1;
    __half* o0 = ao + (size_t)(s0 + pr + g) * D_DIM + h * HD_DIM;
    __half* o8 = o0 + 8 * D_DIM;
    #pragma unroll
    for (int n = 0; n < 8; n++) {
        *(uint32_t*)(o0 + 8 * n + 2 * t) = h2pack(out[n][0] * i0, out[n][1] * i0);
        *(uint32_t*)(o8 + 8 * n + 2 * t) = h2pack(out[n][2] * i1, out[n][3] * i1);
    }
}

// ---------------- driver ----------------
extern "C" void kernel_launch(void* const* d_in, const int* in_sizes, int n_in,
                              void* d_out, int out_size) {
    const float* hidden = (const float*)d_in[0];
    const int*   cu     = (const int*)d_in[1];
    const float* cosp   = (const float*)d_in[2];
    const float* sinp   = (const float*)d_in[3];
    const float* ln1_g  = (const float*)d_in[4];
    const float* ln1_b  = (const float*)d_in[5];
    const float* qkv_w  = (const float*)d_in[6];
    const float* qkv_b  = (const float*)d_in[7];
    const float* proj_w = (const float*)d_in[8];
    const float* proj_b = (const float*)d_in[9];
    const float* ln2_g  = (const float*)d_in[10];
    const float* ln2_b  = (const float*)d_in[11];
    const float* fc1_w  = (const float*)d_in[12];
    const float* fc1_b  = (const float*)d_in[13];
    const float* fc2_w  = (const float*)d_in[14];
    const float* fc2_b  = (const float*)d_in[15];

    float* x = (float*)d_out;

    __half *h, *qkv, *ao, *ff, *wq, *wp, *w1, *w2;
    cudaGetSymbolAddress((void**)&h,   g_h);
    cudaGetSymbolAddress((void**)&qkv, g_qkv);
    cudaGetSymbolAddress((void**)&ao,  g_ao);
    cudaGetSymbolAddress((void**)&ff,  g_ff);
    cudaGetSymbolAddress((void**)&wq,  g_wq);
    cudaGetSymbolAddress((void**)&wp,  g_wp);
    cudaGetSymbolAddress((void**)&w1,  g_w1);
    cudaGetSymbolAddress((void**)&w2,  g_w2);

    cudaFuncSetAttribute(gemm_f16_kernel<0, 128, __half>,
                         cudaFuncAttributeMaxDynamicSharedMemorySize, GSMEM_BYTES(128));
    cudaFuncSetAttribute(gemm_f16_kernel<1, 128, __half>,
                         cudaFuncAttributeMaxDynamicSharedMemorySize, GSMEM_BYTES(128));
    cudaFuncSetAttribute(gemm_f16_kernel<2, 64, float>,
                         cudaFuncAttributeMaxDynamicSharedMemorySize, GSMEM_BYTES(64));

    // fused weight conversion (fp32 -> fp16), 16 elems/thread
    {
        const int n0 = DEPTH * D_DIM * 3 * D_DIM / 16;
        const int n1 = DEPTH * D_DIM * D_DIM / 16;
        const int n2 = DEPTH * D_DIM * FF_DIM / 16;
        const int n3 = DEPTH * FF_DIM * D_DIM / 16;
        const int total = n0 + n1 + n2 + n3;
        f2h_all_kernel<<<(total + 255) / 256, 256>>>(
            qkv_w, wq, n0, proj_w, wp, n1, fc1_w, w1, n2, fc2_w, w2, n3);
    }

    cudaMemcpyAsync(x, hidden, (size_t)S_LEN * D_DIM * sizeof(float),
                    cudaMemcpyDeviceToDevice);

    for (int i = 0; i < DEPTH; i++) {
        const __half* wqi = wq + (size_t)i * D_DIM * 3 * D_DIM;
        const float*  qb  = qkv_b  + (size_t)i * 3 * D_DIM;
        const __half* wpi = wp + (size_t)i * D_DIM * D_DIM;
        const float*  pb  = proj_b + (size_t)i * D_DIM;
        const __half* w1i = w1 + (size_t)i * D_DIM * FF_DIM;
        const float*  f1b = fc1_b  + (size_t)i * FF_DIM;
        const __half* w2i = w2 + (size_t)i * FF_DIM * D_DIM;
        const float*  f2b = fc2_b  + (size_t)i * D_DIM;

        ln_kernel<<<S_LEN / 8, 256>>>(x, ln1_g + (size_t)i * D_DIM,
                                      ln1_b + (size_t)i * D_DIM, h);

        {   // qkv = h @ qkv_w + qkv_b  (half out, BM=128)
            dim3 grid(3 * D_DIM / 128, S_LEN / 128);
            gemm_f16_kernel<0, 128, __half><<<grid, 256, GSMEM_BYTES(128)>>>(
                h, wqi, qb, nullptr, qkv, S_LEN, 3 * D_DIM, D_DIM);
        }

        {   // RoPE (half)
            int total = S_LEN * H_NUM * 16;
            rope_kernel<<<(total + 255) / 256, 256>>>(qkv, cosp, sinp);
        }

        {   // attention -> half ao
            dim3 grid(S_LEN / 128, H_NUM);
            attn_kernel<<<grid, 256>>>(qkv, cu, ao);
        }

        {   // x += ao @ proj_w + proj_b  (fp32 out, BM=64 for occupancy)
            dim3 grid(D_DIM / 128, S_LEN / 64);
            gemm_f16_kernel<2, 64, float><<<grid, 256, GSMEM_BYTES(64)>>>(
                ao, wpi, pb, x, x, S_LEN, D_DIM, D_DIM);
        }

        ln_kernel<<<S_LEN / 8, 256>>>(x, ln2_g + (size_t)i * D_DIM,
                                      ln2_b + (size_t)i * D_DIM, h);

        {   // ff = gelu(h @ fc1_w + fc1_b)  (half out, BM=128)
            dim3 grid(FF_DIM / 128, S_LEN / 128);
            gemm_f16_kernel<1, 128, __half><<<grid, 256, GSMEM_BYTES(128)>>>(
                h, w1i, f1b, nullptr, ff, S_LEN, FF_DIM, D_DIM);
        }

        {   // x += ff @ fc2_w + fc2_b  (fp32 out, BM=64 for occupancy)
            dim3 grid(D_DIM / 128, S_LEN / 64);
            gemm_f16_kernel<2, 64, float><<<grid, 256, GSMEM_BYTES(64)>>>(
                ff, w2i, f2b, x, x, S_LEN, D_DIM, FF_DIM);
        }
    }
}

// round 14
// speedup vs baseline: 1.0021x; 1.0021x over previous
#include <cuda_runtime.h>
#include <cuda_fp16.h>
#include <math.h>
#include <stdint.h>

#define S_LEN 2048
#define D_DIM 1024
#define H_NUM 16
#define HD_DIM 64
#define FF_DIM 4096
#define DEPTH 2
#define NSEG 4
#define EPS 1e-6f

// ---------------- scratch (device globals; allocation-free) ----------------
__device__ __half g_h  [S_LEN * D_DIM];          // LN output (half)
__device__ __half g_qkv[S_LEN * 3 * D_DIM];      // qkv projection (half)
__device__ __half g_ao [S_LEN * D_DIM];          // attention output (half)
__device__ __half g_ff [S_LEN * FF_DIM];         // fc1+gelu output (half)
// half weights [K, N] row-major
__device__ __half g_wq[DEPTH * D_DIM * 3 * D_DIM];
__device__ __half g_wp[DEPTH * D_DIM * D_DIM];
__device__ __half g_w1[DEPTH * D_DIM * FF_DIM];
__device__ __half g_w2[DEPTH * FF_DIM * D_DIM];

// ---------------- helpers ----------------
__device__ __forceinline__ void mma_f16(float* d, const uint32_t* a, const uint32_t* b) {
    asm volatile(
        "mma.sync.aligned.m16n8k16.row.col.f32.f16.f16.f32 "
        "{%0,%1,%2,%3}, {%4,%5,%6,%7}, {%8,%9}, {%0,%1,%2,%3};\n"
        : "+f"(d[0]), "+f"(d[1]), "+f"(d[2]), "+f"(d[3])
        : "r"(a[0]), "r"(a[1]), "r"(a[2]), "r"(a[3]), "r"(b[0]), "r"(b[1]));
}
__device__ __forceinline__ void mma_f16_2(float* d,
                                          uint32_t a0, uint32_t a1, uint32_t a2, uint32_t a3,
                                          uint32_t b0, uint32_t b1) {
    asm volatile(
        "mma.sync.aligned.m16n8k16.row.col.f32.f16.f16.f32 "
        "{%0,%1,%2,%3}, {%4,%5,%6,%7}, {%8,%9}, {%0,%1,%2,%3};\n"
        : "+f"(d[0]), "+f"(d[1]), "+f"(d[2]), "+f"(d[3])
        : "r"(a0), "r"(a1), "r"(a2), "r"(a3), "r"(b0), "r"(b1));
}
__device__ __forceinline__ void ldsm_x4(uint32_t* r, const void* p) {
    uint32_t a = (uint32_t)__cvta_generic_to_shared(p);
    asm volatile("ldmatrix.sync.aligned.m8n8.x4.shared.b16 {%0,%1,%2,%3}, [%4];"
                 : "=r"(r[0]), "=r"(r[1]), "=r"(r[2]), "=r"(r[3]) : "r"(a));
}
__device__ __forceinline__ void ldsm_x4_t(uint32_t* r, const void* p) {
    uint32_t a = (uint32_t)__cvta_generic_to_shared(p);
    asm volatile("ldmatrix.sync.aligned.m8n8.x4.trans.shared.b16 {%0,%1,%2,%3}, [%4];"
                 : "=r"(r[0]), "=r"(r[1]), "=r"(r[2]), "=r"(r[3]) : "r"(a));
}
__device__ __forceinline__ void cp16(void* dst, const void* src) {
    uint32_t d = (uint32_t)__cvta_generic_to_shared(dst);
    asm volatile("cp.async.cg.shared.global [%0], [%1], 16;\n" :: "r"(d), "l"(src));
}
__device__ __forceinline__ void cp_commit() {
    asm volatile("cp.async.commit_group;\n");
}
__device__ __forceinline__ uint32_t h2pack(float a, float b) {
    __half2 h = __floats2half2_rn(a, b);
    return *(uint32_t*)&h;
}

// ------------- fused fp32 -> fp16 conversion, 16 elems/thread --------------
__device__ __forceinline__ void cvt16(const float4* s, uint4* d, int j) {
    float4 a = s[4 * j], b = s[4 * j + 1], c = s[4 * j + 2], e = s[4 * j + 3];
    uint4 o0, o1;
    o0.x = h2pack(a.x, a.y); o0.y = h2pack(a.z, a.w);
    o0.z = h2pack(b.x, b.y); o0.w = h2pack(b.z, b.w);
    o1.x = h2pack(c.x, c.y); o1.y = h2pack(c.z, c.w);
    o1.z = h2pack(e.x, e.y); o1.w = h2pack(e.z, e.w);
    d[2 * j] = o0; d[2 * j + 1] = o1;
}
__global__ void f2h_all_kernel(const float* w0, __half* o0, int n0,   // in 16-elem units
                               const float* w1, __half* o1, int n1,
                               const float* w2, __half* o2, int n2,
                               const float* w3, __half* o3, int n3) {
    int i = blockIdx.x * blockDim.x + threadIdx.x;
    if (i < n0) { cvt16((const float4*)w0, (uint4*)o0, i); return; }
    i -= n0;
    if (i < n1) { cvt16((const float4*)w1, (uint4*)o1, i); return; }
    i -= n1;
    if (i < n2) { cvt16((const float4*)w2, (uint4*)o2, i); return; }
    i -= n2;
    if (i < n3) { cvt16((const float4*)w3, (uint4*)o3, i); }
}

// ---------------- LayerNorm: one WARP per row, half output -----------------
__global__ __launch_bounds__(256)
void ln_kernel(const float* __restrict__ x,
               const float* __restrict__ g,
               const float* __restrict__ b,
               __half* __restrict__ out) {
    const int lane = threadIdx.x & 31;
    const int row  = blockIdx.x * 8 + (threadIdx.x >> 5);
    const float* xr = x + (size_t)row * D_DIM;

    float4 v[8];
    float s = 0.f;
    #pragma unroll
    for (int i = 0; i < 8; i++) {
        v[i] = *(const float4*)(xr + i * 128 + lane * 4);
        s += v[i].x + v[i].y + v[i].z + v[i].w;
    }
    #pragma unroll
    for (int o = 16; o > 0; o >>= 1) s += __shfl_xor_sync(0xffffffffu, s, o);
    const float mean = s * (1.f / D_DIM);

    float var = 0.f;
    #pragma unroll
    for (int i = 0; i < 8; i++) {
        float dx = v[i].x - mean, dy = v[i].y - mean;
        float dz = v[i].z - mean, dw = v[i].w - mean;
        var += dx * dx + dy * dy + dz * dz + dw * dw;
    }
    #pragma unroll
    for (int o = 16; o > 0; o >>= 1) var += __shfl_xor_sync(0xffffffffu, var, o);
    const float rstd = rsqrtf(var * (1.f / D_DIM) + EPS);

    __half* orow = out + (size_t)row * D_DIM;
    #pragma unroll
    for (int i = 0; i < 8; i++) {
        const int col = i * 128 + lane * 4;
        float4 gv = *(const float4*)(g + col);
        float4 bv = *(const float4*)(b + col);
        uint2 o;
        o.x = h2pack((v[i].x - mean) * rstd * gv.x + bv.x,
                     (v[i].y - mean) * rstd * gv.y + bv.y);
        o.y = h2pack((v[i].z - mean) * rstd * gv.z + bv.z,
                     (v[i].w - mean) * rstd * gv.w + bv.w);
        *(uint2*)(orow + col) = o;
    }
}

// ---- FP16 GEMM: BMx128 tile (BM=128 or 64), BK=64, 2-stage cp.async ----
// Warp layout: WM = BM/64 warps over M, WN = 8/WM over N; warp tile 64 x 128/WN.
// EPI: 0 = bias (CT out), 1 = bias + exact GELU (half C), 2 = bias+resid (float C)
#define GSMEM_BYTES(BM) ((2 * (BM) * 72 + 2 * 64 * 136) * 2)
template<int EPI, int BM, typename CT>
__global__ __launch_bounds__(256)
void gemm_f16_kernel(const __half* __restrict__ A,
                     const __half* __restrict__ B,
                     const float* __restrict__ bias,
                     const float* __restrict__ resid,
                     CT* __restrict__ C,
                     int M, int N, int K) {
    constexpr int WM = BM / 64;          // 2 or 1
    constexpr int WN = 8 / WM;           // 4 or 8
    constexpr int NW = 128 / WN;         // 32 or 16 cols per warp
    constexpr int NP = NW / 16;          // 2 or 1 B-ldsm per k16
    constexpr int NI = 2 * NP;           // 4 or 2 acc n-frags

    extern __shared__ __half gsm[];
    __half (*As)[BM][72]  = (__half(*)[BM][72])gsm;
    __half (*Bs)[64][136] = (__half(*)[64][136])(gsm + 2 * BM * 72);

    const int tid  = threadIdx.x;
    const int lane = tid & 31;
    const int wid  = tid >> 5;
    const int warp_m = wid / WN;
    const int warp_n = wid % WN;
    const int g = lane >> 2;
    const int t = lane & 3;

    const int bx = blockIdx.x;
    const int by = blockIdx.y;

    const __half* Ag = A + (size_t)by * BM * K;
    const __half* Bg = B + (size_t)bx * 128;

    float acc[4][NI][4];
    #pragma unroll
    for (int mi = 0; mi < 4; mi++)
        #pragma unroll
        for (int ni = 0; ni < NI; ni++)
            #pragma unroll
            for (int e = 0; e < 4; e++) acc[mi][ni][e] = 0.f;

    const int NIT = K >> 6;    // BK = 64

    auto load_stage = [&](int st, int k0) {
        #pragma unroll
        for (int i = 0; i < BM / 32; i++) {
            int id = tid + 256 * i;
            int r = id >> 3, c = (id & 7) * 8;
            cp16(&As[st][r][c], Ag + (size_t)r * K + k0 + c);
        }
        #pragma unroll
        for (int i = 0; i < 4; i++) {
            int id = tid + 256 * i;
            int r = id >> 4, c = (id & 15) * 8;
            cp16(&Bs[st][r][c], Bg + (size_t)(k0 + r) * N + c);
        }
        cp_commit();
    };

    load_stage(0, 0);

    const int a_row = lane & 15;
    const int a_chk = (lane >> 4) * 8;

    #pragma unroll 1
    for (int it = 0; it < NIT; it++) {
        const int buf = it & 1;
        asm volatile("cp.async.wait_group 0;\n");
        __syncthreads();
        if (it + 1 < NIT) load_stage(buf ^ 1, (it + 1) << 6);

        #pragma unroll
        for (int ks = 0; ks < 4; ks++) {
            uint32_t af[4][4], bf[NI][2];
            #pragma unroll
            for (int mi = 0; mi < 4; mi++) {
                int row = warp_m * 64 + mi * 16 + a_row;
                ldsm_x4(af[mi], &As[buf][row][ks * 16 + a_chk]);
            }
            #pragma unroll
            for (int p = 0; p < NP; p++) {
                uint32_t r[4];
                int krow = ks * 16 + a_row;
                int ncol = warp_n * NW + p * 16 + a_chk;
                ldsm_x4_t(r, &Bs[buf][krow][ncol]);
                bf[p * 2][0] = r[0]; bf[p * 2][1] = r[1];
                bf[p * 2 + 1][0] = r[2]; bf[p * 2 + 1][1] = r[3];
            }
            #pragma unroll
            for (int mi = 0; mi < 4; mi++)
                #pragma unroll
                for (int ni = 0; ni < NI; ni++)
                    mma_f16(acc[mi][ni], af[mi], bf[ni]);
        }
    }

    #pragma unroll
    for (int mi = 0; mi < 4; mi++) {
        const int row0 = by * BM + warp_m * 64 + mi * 16 + g;
        #pragma unroll
        for (int ni = 0; ni < NI; ni++) {
            const int col = bx * 128 + warp_n * NW + (ni >> 1) * 16 + (ni & 1) * 8 + 2 * t;
            #pragma unroll
            for (int half_ = 0; half_ < 2; half_++) {
                const int r = row0 + half_ * 8;
                float v0 = acc[mi][ni][half_ * 2]     + bias[col];
                float v1 = acc[mi][ni][half_ * 2 + 1] + bias[col + 1];
                if (EPI == 1) {
                    v0 = 0.5f * v0 * (1.f + erff(v0 * 0.70710678118654752f));
                    v1 = 0.5f * v1 * (1.f + erff(v1 * 0.70710678118654752f));
                } else if (EPI == 2) {
                    const float* rr = resid + (size_t)r * N + col;
                    v0 += rr[0]; v1 += rr[1];
                }
                if (sizeof(CT) == 2) {
                    *(uint32_t*)((__half*)C + (size_t)r * N + col) = h2pack(v0, v1);
                } else {
                    ((float*)C)[(size_t)r * N + col]     = v0;
                    ((float*)C)[(size_t)r * N + col + 1] = v1;
                }
            }
        }
    }
}

// ---------------- RoPE on q and k slices of half qkv ----------------
__global__ void rope_kernel(__half* __restrict__ qkv,
                            const float* __restrict__ cosp,
                            const float* __restrict__ sinp) {
    int idx = blockIdx.x * blockDim.x + threadIdx.x;  // S*H*16
    if (idx >= S_LEN * H_NUM * 16) return;
    const int d2 = (idx & 15) * 2;
    const int h = (idx >> 4) & (H_NUM - 1);
    const int s = idx >> 8;

    const float2 c1 = *(const float2*)(cosp + s * 64 + d2);
    const float2 c2 = *(const float2*)(cosp + s * 64 + d2 + 32);
    const float2 s1 = *(const float2*)(sinp + s * 64 + d2);
    const float2 s2 = *(const float2*)(sinp + s * 64 + d2 + 32);

    __half* base = qkv + (size_t)s * (3 * D_DIM) + h * HD_DIM + d2;
    #pragma unroll
    for (int qk = 0; qk < 2; qk++) {
        __half* p = base + qk * D_DIM;
        float2 a = __half22float2(*(__half2*)p);
        float2 bv = __half22float2(*(__half2*)(p + 32));
        *(uint32_t*)p        = h2pack(a.x * c1.x - bv.x * s1.x,
                                      a.y * c1.y - bv.y * s1.y);
        *(uint32_t*)(p + 32) = h2pack(bv.x * c2.x + a.x * s2.x,
                                      bv.y * c2.y + a.y * s2.y);
    }
}

// ---- fp16 flash attention, double-buffered cp.async K/V chunks ----
__global__ __launch_bounds__(256)
void attn_kernel(const __half* __restrict__ qkv,
                 const int* __restrict__ cu,
                 __half* __restrict__ ao) {
    const int h  = blockIdx.y;
    const int s0 = blockIdx.x * 128;
    const int tid  = threadIdx.x;
    const int lane = tid & 31;
    const int wid  = tid >> 5;
    const int g = lane >> 2;
    const int t = lane & 3;
    const int a_row = lane & 15;
    const int a_chk = (lane >> 4) * 8;

    __shared__ __half Kh[2][32][72];
    __shared__ __half Vh[2][32][72];

    int start = 0, len = S_LEN;
    #pragma unroll
    for (int i = 0; i < NSEG; i++) {
        int a = cu[i], b = cu[i + 1];
        if (s0 >= a && s0 < b) { start = a; len = b - a; }
    }

    const int pr = wid * 16;

    uint32_t qf[4][4];
    {
        const __half* q0 = qkv + (size_t)(s0 + pr + g) * (3 * D_DIM) + h * HD_DIM;
        const __half* q8 = q0 + 8 * (3 * D_DIM);
        #pragma unroll
        for (int dc = 0; dc < 4; dc++) {
            const int c = dc * 16 + 2 * t;
            qf[dc][0] = *(const uint32_t*)(q0 + c);
            qf[dc][1] = *(const uint32_t*)(q8 + c);
            qf[dc][2] = *(const uint32_t*)(q0 + c + 8);
            qf[dc][3] = *(const uint32_t*)(q8 + c + 8);
        }
    }

    float m0 = -3.4e38f, m1 = -3.4e38f, l0 = 0.f, l1 = 0.f;
    float out[8][4];
    #pragma unroll
    for (int n = 0; n < 8; n++)
        #pragma unroll
        for (int e = 0; e < 4; e++) out[n][e] = 0.f;

    const int kr = tid >> 3;
    const int kc8 = (tid & 7) * 8;
    auto load_chunk = [&](int buf, int kb) {
        const __half* base = qkv + (size_t)(kb + kr) * (3 * D_DIM) + h * HD_DIM + kc8;
        cp16(&Kh[buf][kr][kc8], base + D_DIM);
        cp16(&Vh[buf][kr][kc8], base + 2 * D_DIM);
        cp_commit();
    };

    load_chunk(0, start);

    const int nch = len >> 5;
    for (int c = 0; c < nch; c++) {
        const int buf = c & 1;
        asm volatile("cp.async.wait_group 0;\n");
        __syncthreads();
        if (c + 1 < nch) load_chunk(buf ^ 1, start + (c + 1) * 32);

        // S = Q @ K^T
        float sacc[4][4];
        #pragma unroll
        for (int j = 0; j < 4; j++)
            #pragma unroll
            for (int e = 0; e < 4; e++) sacc[j][e] = 0.f;
        #pragma unroll
        for (int dc = 0; dc < 4; dc++) {
            #pragma unroll
            for (int kh = 0; kh < 2; kh++) {
                uint32_t r[4];
                ldsm_x4(r, &Kh[buf][kh * 16 + a_row][dc * 16 + a_chk]);
                mma_f16_2(sacc[kh * 2],     qf[dc][0], qf[dc][1], qf[dc][2], qf[dc][3],
                          r[0], r[2]);
                mma_f16_2(sacc[kh * 2 + 1], qf[dc][0], qf[dc][1], qf[dc][2], qf[dc][3],
                          r[1], r[3]);
            }
        }
        #pragma unroll
        for (int j = 0; j < 4; j++)
            #pragma unroll
            for (int e = 0; e < 4; e++) sacc[j][e] *= 0.125f;

        // online softmax
        float ml0 = -3.4e38f, ml1 = -3.4e38f;
        #pragma unroll
        for (int j = 0; j < 4; j++) {
            ml0 = fmaxf(ml0, fmaxf(sacc[j][0], sacc[j][1]));
            ml1 = fmaxf(ml1, fmaxf(sacc[j][2], sacc[j][3]));
        }
        ml0 = fmaxf(ml0, __shfl_xor_sync(0xffffffffu, ml0, 1));
        ml0 = fmaxf(ml0, __shfl_xor_sync(0xffffffffu, ml0, 2));
        ml1 = fmaxf(ml1, __shfl_xor_sync(0xffffffffu, ml1, 1));
        ml1 = fmaxf(ml1, __shfl_xor_sync(0xffffffffu, ml1, 2));
        const float mn0 = fmaxf(m0, ml0);
        const float mn1 = fmaxf(m1, ml1);
        const float f0 = __expf(m0 - mn0);
        const float f1 = __expf(m1 - mn1);

        uint32_t pa[2][4];
        float ll0 = 0.f, ll1 = 0.f;
        #pragma unroll
        for (int j = 0; j < 4; j++) {
            float p0 = __expf(sacc[j][0] - mn0);
            float p1 = __expf(sacc[j][1] - mn0);
            float p2 = __expf(sacc[j][2] - mn1);
            float p3 = __expf(sacc[j][3] - mn1);
            ll0 += p0 + p1; ll1 += p2 + p3;
            pa[j >> 1][(j & 1) * 2]     = h2pack(p0, p1);
            pa[j >> 1][(j & 1) * 2 + 1] = h2pack(p2, p3);
        }
        ll0 += __shfl_xor_sync(0xffffffffu, ll0, 1);
        ll0 += __shfl_xor_sync(0xffffffffu, ll0, 2);
        ll1 += __shfl_xor_sync(0xffffffffu, ll1, 1);
        ll1 += __shfl_xor_sync(0xffffffffu, ll1, 2);
        l0 = l0 * f0 + ll0;
        l1 = l1 * f1 + ll1;
        m0 = mn0; m1 = mn1;
        #pragma unroll
        for (int n = 0; n < 8; n++) {
            out[n][0] *= f0; out[n][1] *= f0;
            out[n][2] *= f1; out[n][3] *= f1;
        }

        // out += P @ V
        #pragma unroll
        for (int kc = 0; kc < 2; kc++) {
            #pragma unroll
            for (int p = 0; p < 4; p++) {
                uint32_t r[4];
                ldsm_x4_t(r, &Vh[buf][kc * 16 + a_row][p * 16 + a_chk]);
                mma_f16(out[p * 2], pa[kc], r);
                mma_f16_2(out[p * 2 + 1], pa[kc][0], pa[kc][1], pa[kc][2], pa[kc][3],
                          r[2], r[3]);
            }
        }
    }

    const float i0 = 1.f / l0;
    const float i1 = 1.f / l1;
    __half* o0 = ao + (size_t)(s0 + pr + g) * D_DIM + h * HD_DIM;
    __half* o8 = o0 + 8 * D_DIM;
    #pragma unroll
    for (int n = 0; n < 8; n++) {
        *(uint32_t*)(o0 + 8 * n + 2 * t) = h2pack(out[n][0] * i0, out[n][1] * i0);
        *(uint32_t*)(o8 + 8 * n + 2 * t) = h2pack(out[n][2] * i1, out[n][3] * i1);
    }
}

// ---------------- driver ----------------
extern "C" void kernel_launch(void* const* d_in, const int* in_sizes, int n_in,
                              void* d_out, int out_size) {
    const float* hidden = (const float*)d_in[0];
    const int*   cu     = (const int*)d_in[1];
    const float* cosp   = (const float*)d_in[2];
    const float* sinp   = (const float*)d_in[3];
    const float* ln1_g  = (const float*)d_in[4];
    const float* ln1_b  = (const float*)d_in[5];
    const float* qkv_w  = (const float*)d_in[6];
    const float* qkv_b  = (const float*)d_in[7];
    const float* proj_w = (const float*)d_in[8];
    const float* proj_b = (const float*)d_in[9];
    const float* ln2_g  = (const float*)d_in[10];
    const float* ln2_b  = (const float*)d_in[11];
    const float* fc1_w  = (const float*)d_in[12];
    const float* fc1_b  = (const float*)d_in[13];
    const float* fc2_w  = (const float*)d_in[14];
    const float* fc2_b  = (const float*)d_in[15];

    float* x = (float*)d_out;

    __half *h, *qkv, *ao, *ff, *wq, *wp, *w1, *w2;
    cudaGetSymbolAddress((void**)&h,   g_h);
    cudaGetSymbolAddress((void**)&qkv, g_qkv);
    cudaGetSymbolAddress((void**)&ao,  g_ao);
    cudaGetSymbolAddress((void**)&ff,  g_ff);
    cudaGetSymbolAddress((void**)&wq,  g_wq);
    cudaGetSymbolAddress((void**)&wp,  g_wp);
    cudaGetSymbolAddress((void**)&w1,  g_w1);
    cudaGetSymbolAddress((void**)&w2,  g_w2);

    cudaFuncSetAttribute(gemm_f16_kernel<0, 128, __half>,
                         cudaFuncAttributeMaxDynamicSharedMemorySize, GSMEM_BYTES(128));
    cudaFuncSetAttribute(gemm_f16_kernel<1, 128, __half>,
                         cudaFuncAttributeMaxDynamicSharedMemorySize, GSMEM_BYTES(128));
    cudaFuncSetAttribute(gemm_f16_kernel<2, 64, float>,
                         cudaFuncAttributeMaxDynamicSharedMemorySize, GSMEM_BYTES(64));

    // fused weight conversion (fp32 -> fp16), 16 elems/thread
    {
        const int n0 = DEPTH * D_DIM * 3 * D_DIM / 16;
        const int n1 = DEPTH * D_DIM * D_DIM / 16;
        const int n2 = DEPTH * D_DIM * FF_DIM / 16;
        const int n3 = DEPTH * FF_DIM * D_DIM / 16;
        const int total = n0 + n1 + n2 + n3;
        f2h_all_kernel<<<(total + 255) / 256, 256>>>(
            qkv_w, wq, n0, proj_w, wp, n1, fc1_w, w1, n2, fc2_w, w2, n3);
    }

    cudaMemcpyAsync(x, hidden, (size_t)S_LEN * D_DIM * sizeof(float),
                    cudaMemcpyDeviceToDevice);

    for (int i = 0; i < DEPTH; i++) {
        const __half* wqi = wq + (size_t)i * D_DIM * 3 * D_DIM;
        const float*  qb  = qkv_b  + (size_t)i * 3 * D_DIM;
        const __half* wpi = wp + (size_t)i * D_DIM * D_DIM;
        const float*  pb  = proj_b + (size_t)i * D_DIM;
        const __half* w1i = w1 + (size_t)i * D_DIM * FF_DIM;
        const float*  f1b = fc1_b  + (size_t)i * FF_DIM;
        const __half* w2i = w2 + (size_t)i * FF_DIM * D_DIM;
        const float*  f2b = fc2_b  + (size_t)i * D_DIM;

        ln_kernel<<<S_LEN / 8, 256>>>(x, ln1_g + (size_t)i * D_DIM,
                                      ln1_b + (size_t)i * D_DIM, h);

        {   // qkv = h @ qkv_w + qkv_b  (half out, BM=128)
            dim3 grid(3 * D_DIM / 128, S_LEN / 128);
            gemm_f16_kernel<0, 128, __half><<<grid, 256, GSMEM_BYTES(128)>>>(
                h, wqi, qb, nullptr, qkv, S_LEN, 3 * D_DIM, D_DIM);
        }

        {   // RoPE (half)
            int total = S_LEN * H_NUM * 16;
            rope_kernel<<<(total + 255) / 256, 256>>>(qkv, cosp, sinp);
        }

        {   // attention -> half ao
            dim3 grid(S_LEN / 128, H_NUM);
            attn_kernel<<<grid, 256>>>(qkv, cu, ao);
        }

        {   // x += ao @ proj_w + proj_b  (fp32 out, BM=64 for occupancy)
            dim3 grid(D_DIM / 128, S_LEN / 64);
            gemm_f16_kernel<2, 64, float><<<grid, 256, GSMEM_BYTES(64)>>>(
                ao, wpi, pb, x, x, S_LEN, D_DIM, D_DIM);
        }

        ln_kernel<<<S_LEN / 8, 256>>>(x, ln2_g + (size_t)i * D_DIM,
                                      ln2_b + (size_t)i * D_DIM, h);

        {   // ff = gelu(h @ fc1_w + fc1_b)  (half out, BM=128)
            dim3 grid(FF_DIM / 128, S_LEN / 128);
            gemm_f16_kernel<1, 128, __half><<<grid, 256, GSMEM_BYTES(128)>>>(
                h, w1i, f1b, nullptr, ff, S_LEN, FF_DIM, D_DIM);
        }

        {   // x += ff @ fc2_w + fc2_b  (fp32 out, BM=64 for occupancy)
            dim3 grid(D_DIM / 128, S_LEN / 64);
            gemm_f16_kernel<2, 64, float><<<grid, 256, GSMEM_BYTES(64)>>>(
                ff, w2i, f2b, x, x, S_LEN, D_DIM, FF_DIM);
        }
    }
}

// round 15
// speedup vs baseline: 1.0581x; 1.0559x over previous
#include <cuda_runtime.h>
#include <cuda_fp16.h>
#include <math.h>
#include <stdint.h>

#define S_LEN 2048
#define D_DIM 1024
#define H_NUM 16
#define HD_DIM 64
#define FF_DIM 4096
#define DEPTH 2
#define NSEG 4
#define EPS 1e-6f

// ---------------- scratch (device globals; allocation-free) ----------------
__device__ __half g_h  [S_LEN * D_DIM];          // LN output (half)
__device__ __half g_qkv[S_LEN * 3 * D_DIM];      // qkv projection (half)
__device__ __half g_ao [S_LEN * D_DIM];          // attention output (half)
__device__ __half g_ff [S_LEN * FF_DIM];         // fc1+gelu output (half)
// half weights [K, N] row-major
__device__ __half g_wq[DEPTH * D_DIM * 3 * D_DIM];
__device__ __half g_wp[DEPTH * D_DIM * D_DIM];
__device__ __half g_w1[DEPTH * D_DIM * FF_DIM];
__device__ __half g_w2[DEPTH * FF_DIM * D_DIM];

// ---------------- helpers ----------------
__device__ __forceinline__ void mma_f16(float* d, const uint32_t* a, const uint32_t* b) {
    asm volatile(
        "mma.sync.aligned.m16n8k16.row.col.f32.f16.f16.f32 "
        "{%0,%1,%2,%3}, {%4,%5,%6,%7}, {%8,%9}, {%0,%1,%2,%3};\n"
        : "+f"(d[0]), "+f"(d[1]), "+f"(d[2]), "+f"(d[3])
        : "r"(a[0]), "r"(a[1]), "r"(a[2]), "r"(a[3]), "r"(b[0]), "r"(b[1]));
}
__device__ __forceinline__ void mma_f16_2(float* d,
                                          uint32_t a0, uint32_t a1, uint32_t a2, uint32_t a3,
                                          uint32_t b0, uint32_t b1) {
    asm volatile(
        "mma.sync.aligned.m16n8k16.row.col.f32.f16.f16.f32 "
        "{%0,%1,%2,%3}, {%4,%5,%6,%7}, {%8,%9}, {%0,%1,%2,%3};\n"
        : "+f"(d[0]), "+f"(d[1]), "+f"(d[2]), "+f"(d[3])
        : "r"(a0), "r"(a1), "r"(a2), "r"(a3), "r"(b0), "r"(b1));
}
__device__ __forceinline__ void ldsm_x4(uint32_t* r, const void* p) {
    uint32_t a = (uint32_t)__cvta_generic_to_shared(p);
    asm volatile("ldmatrix.sync.aligned.m8n8.x4.shared.b16 {%0,%1,%2,%3}, [%4];"
                 : "=r"(r[0]), "=r"(r[1]), "=r"(r[2]), "=r"(r[3]) : "r"(a));
}
__device__ __forceinline__ void ldsm_x4_t(uint32_t* r, const void* p) {
    uint32_t a = (uint32_t)__cvta_generic_to_shared(p);
    asm volatile("ldmatrix.sync.aligned.m8n8.x4.trans.shared.b16 {%0,%1,%2,%3}, [%4];"
                 : "=r"(r[0]), "=r"(r[1]), "=r"(r[2]), "=r"(r[3]) : "r"(a));
}
__device__ __forceinline__ void cp16(void* dst, const void* src) {
    uint32_t d = (uint32_t)__cvta_generic_to_shared(dst);
    asm volatile("cp.async.cg.shared.global [%0], [%1], 16;\n" :: "r"(d), "l"(src));
}
__device__ __forceinline__ void cp_commit() {
    asm volatile("cp.async.commit_group;\n");
}
__device__ __forceinline__ uint32_t h2pack(float a, float b) {
    __half2 h = __floats2half2_rn(a, b);
    return *(uint32_t*)&h;
}

// ------------- fused fp32 -> fp16 conversion, 16 elems/thread --------------
__device__ __forceinline__ void cvt16(const float4* s, uint4* d, int j) {
    float4 a = s[4 * j], b = s[4 * j + 1], c = s[4 * j + 2], e = s[4 * j + 3];
    uint4 o0, o1;
    o0.x = h2pack(a.x, a.y); o0.y = h2pack(a.z, a.w);
    o0.z = h2pack(b.x, b.y); o0.w = h2pack(b.z, b.w);
    o1.x = h2pack(c.x, c.y); o1.y = h2pack(c.z, c.w);
    o1.z = h2pack(e.x, e.y); o1.w = h2pack(e.z, e.w);
    d[2 * j] = o0; d[2 * j + 1] = o1;
}
__global__ void f2h_all_kernel(const float* w0, __half* o0, int n0,   // in 16-elem units
                               const float* w1, __half* o1, int n1,
                               const float* w2, __half* o2, int n2,
                               const float* w3, __half* o3, int n3) {
    int i = blockIdx.x * blockDim.x + threadIdx.x;
    if (i < n0) { cvt16((const float4*)w0, (uint4*)o0, i); return; }
    i -= n0;
    if (i < n1) { cvt16((const float4*)w1, (uint4*)o1, i); return; }
    i -= n1;
    if (i < n2) { cvt16((const float4*)w2, (uint4*)o2, i); return; }
    i -= n2;
    if (i < n3) { cvt16((const float4*)w3, (uint4*)o3, i); }
}

// ---------------- LayerNorm: one WARP per row, half output -----------------
__global__ __launch_bounds__(256)
void ln_kernel(const float* __restrict__ x,
               const float* __restrict__ g,
               const float* __restrict__ b,
               __half* __restrict__ out) {
    const int lane = threadIdx.x & 31;
    const int row  = blockIdx.x * 8 + (threadIdx.x >> 5);
    const float* xr = x + (size_t)row * D_DIM;

    float4 v[8];
    float s = 0.f;
    #pragma unroll
    for (int i = 0; i < 8; i++) {
        v[i] = *(const float4*)(xr + i * 128 + lane * 4);
        s += v[i].x + v[i].y + v[i].z + v[i].w;
    }
    #pragma unroll
    for (int o = 16; o > 0; o >>= 1) s += __shfl_xor_sync(0xffffffffu, s, o);
    const float mean = s * (1.f / D_DIM);

    float var = 0.f;
    #pragma unroll
    for (int i = 0; i < 8; i++) {
        float dx = v[i].x - mean, dy = v[i].y - mean;
        float dz = v[i].z - mean, dw = v[i].w - mean;
        var += dx * dx + dy * dy + dz * dz + dw * dw;
    }
    #pragma unroll
    for (int o = 16; o > 0; o >>= 1) var += __shfl_xor_sync(0xffffffffu, var, o);
    const float rstd = rsqrtf(var * (1.f / D_DIM) + EPS);

    __half* orow = out + (size_t)row * D_DIM;
    #pragma unroll
    for (int i = 0; i < 8; i++) {
        const int col = i * 128 + lane * 4;
        float4 gv = *(const float4*)(g + col);
        float4 bv = *(const float4*)(b + col);
        uint2 o;
        o.x = h2pack((v[i].x - mean) * rstd * gv.x + bv.x,
                     (v[i].y - mean) * rstd * gv.y + bv.y);
        o.y = h2pack((v[i].z - mean) * rstd * gv.z + bv.z,
                     (v[i].w - mean) * rstd * gv.w + bv.w);
        *(uint2*)(orow + col) = o;
    }
}

// ------- FP16 GEMM: 128x128 tile, BK=64, 2-stage cp.async (race-free) ------
// EPI: 0 = bias (half C), 1 = bias + exact GELU (half C), 2 = bias+resid (float C)
#define G3_AS_HALFS (2 * 128 * 72)
#define G3_SMEM_BYTES ((2 * 128 * 72 + 2 * 64 * 136) * 2)   // 71680
template<int EPI, typename CT>
__global__ __launch_bounds__(256)
void gemm_f16_kernel(const __half* __restrict__ A,
                     const __half* __restrict__ B,
                     const float* __restrict__ bias,
                     const float* __restrict__ resid,
                     CT* __restrict__ C,
                     int M, int N, int K) {
    extern __shared__ __half gsm[];
    __half (*As)[128][72] = (__half(*)[128][72])gsm;
    __half (*Bs)[64][136] = (__half(*)[64][136])(gsm + G3_AS_HALFS);

    const int tid  = threadIdx.x;
    const int lane = tid & 31;
    const int wid  = tid >> 5;
    const int warp_m = wid & 1;
    const int warp_n = wid >> 1;
    const int g = lane >> 2;
    const int t = lane & 3;

    const int bx = blockIdx.x;
    const int by = blockIdx.y;

    const __half* Ag = A + (size_t)by * 128 * K;
    const __half* Bg = B + (size_t)bx * 128;

    float acc[4][4][4];
    #pragma unroll
    for (int mi = 0; mi < 4; mi++)
        #pragma unroll
        for (int ni = 0; ni < 4; ni++)
            #pragma unroll
            for (int e = 0; e < 4; e++) acc[mi][ni][e] = 0.f;

    const int NIT = K >> 6;    // BK = 64

    auto load_stage = [&](int st, int k0) {
        #pragma unroll
        for (int i = 0; i < 4; i++) {
            int id = tid + 256 * i;
            int r = id >> 3, c = (id & 7) * 8;
            cp16(&As[st][r][c], Ag + (size_t)r * K + k0 + c);
        }
        #pragma unroll
        for (int i = 0; i < 4; i++) {
            int id = tid + 256 * i;
            int r = id >> 4, c = (id & 15) * 8;
            cp16(&Bs[st][r][c], Bg + (size_t)(k0 + r) * N + c);
        }
        cp_commit();
    };

    load_stage(0, 0);

    const int a_row = lane & 15;
    const int a_chk = (lane >> 4) * 8;

    #pragma unroll 1
    for (int it = 0; it < NIT; it++) {
        const int buf = it & 1;
        asm volatile("cp.async.wait_group 0;\n");
        __syncthreads();
        if (it + 1 < NIT) load_stage(buf ^ 1, (it + 1) << 6);

        #pragma unroll
        for (int ks = 0; ks < 4; ks++) {
            uint32_t af[4][4], bf[4][2];
            #pragma unroll
            for (int mi = 0; mi < 4; mi++) {
                int row = warp_m * 64 + mi * 16 + a_row;
                ldsm_x4(af[mi], &As[buf][row][ks * 16 + a_chk]);
            }
            #pragma unroll
            for (int p = 0; p < 2; p++) {
                uint32_t r[4];
                int krow = ks * 16 + a_row;
                int ncol = warp_n * 32 + p * 16 + a_chk;
                ldsm_x4_t(r, &Bs[buf][krow][ncol]);
                bf[p * 2][0] = r[0]; bf[p * 2][1] = r[1];
                bf[p * 2 + 1][0] = r[2]; bf[p * 2 + 1][1] = r[3];
            }
            #pragma unroll
            for (int mi = 0; mi < 4; mi++)
                #pragma unroll
                for (int ni = 0; ni < 4; ni++)
                    mma_f16(acc[mi][ni], af[mi], bf[ni]);
        }
    }

    #pragma unroll
    for (int mi = 0; mi < 4; mi++) {
        const int row0 = by * 128 + warp_m * 64 + mi * 16 + g;
        #pragma unroll
        for (int ni = 0; ni < 4; ni++) {
            const int col = bx * 128 + warp_n * 32 + (ni >> 1) * 16 + (ni & 1) * 8 + 2 * t;
            #pragma unroll
            for (int half_ = 0; half_ < 2; half_++) {
                const int r = row0 + half_ * 8;
                float v0 = acc[mi][ni][half_ * 2]     + bias[col];
                float v1 = acc[mi][ni][half_ * 2 + 1] + bias[col + 1];
                if (EPI == 1) {
                    v0 = 0.5f * v0 * (1.f + erff(v0 * 0.70710678118654752f));
                    v1 = 0.5f * v1 * (1.f + erff(v1 * 0.70710678118654752f));
                } else if (EPI == 2) {
                    float2 rr = *(const float2*)(resid + (size_t)r * N + col);
                    v0 += rr.x; v1 += rr.y;
                }
                if (sizeof(CT) == 2) {
                    *(uint32_t*)((__half*)C + (size_t)r * N + col) = h2pack(v0, v1);
                } else {
                    *(float2*)((float*)C + (size_t)r * N + col) = make_float2(v0, v1);
                }
            }
        }
    }
}

// ---------------- RoPE on K slice only (Q fused into attention) ------------
__global__ void rope_k_kernel(__half* __restrict__ qkv,
                              const float* __restrict__ cosp,
                              const float* __restrict__ sinp) {
    int idx = blockIdx.x * blockDim.x + threadIdx.x;  // S*H*16
    if (idx >= S_LEN * H_NUM * 16) return;
    const int d2 = (idx & 15) * 2;
    const int h = (idx >> 4) & (H_NUM - 1);
    const int s = idx >> 8;

    const float2 c1 = *(const float2*)(cosp + s * 64 + d2);
    const float2 c2 = *(const float2*)(cosp + s * 64 + d2 + 32);
    const float2 s1 = *(const float2*)(sinp + s * 64 + d2);
    const float2 s2 = *(const float2*)(sinp + s * 64 + d2 + 32);

    __half* p = qkv + (size_t)s * (3 * D_DIM) + D_DIM + h * HD_DIM + d2;
    float2 a = __half22float2(*(__half2*)p);
    float2 bv = __half22float2(*(__half2*)(p + 32));
    *(uint32_t*)p        = h2pack(a.x * c1.x - bv.x * s1.x,
                                  a.y * c1.y - bv.y * s1.y);
    *(uint32_t*)(p + 32) = h2pack(bv.x * c2.x + a.x * s2.x,
                                  bv.y * c2.y + a.y * s2.y);
}

// ---- fp16 flash attention, double-buffered cp.async K/V; Q-RoPE fused ----
__global__ __launch_bounds__(256)
void attn_kernel(const __half* __restrict__ qkv,
                 const int* __restrict__ cu,
                 const float* __restrict__ cosp,
                 const float* __restrict__ sinp,
                 __half* __restrict__ ao) {
    const int h  = blockIdx.y;
    const int s0 = blockIdx.x * 128;
    const int tid  = threadIdx.x;
    const int lane = tid & 31;
    const int wid  = tid >> 5;
    const int g = lane >> 2;
    const int t = lane & 3;
    const int a_row = lane & 15;
    const int a_chk = (lane >> 4) * 8;

    __shared__ __half Kh[2][32][72];
    __shared__ __half Vh[2][32][72];

    int start = 0, len = S_LEN;
    #pragma unroll
    for (int i = 0; i < NSEG; i++) {
        int a = cu[i], b = cu[i + 1];
        if (s0 >= a && s0 < b) { start = a; len = b - a; }
    }

    const int pr = wid * 16;

    // Q frags with fused RoPE: thread holds both rotate_half partners (dc and dc^2)
    uint32_t qf[4][4];
    {
        const int r0 = s0 + pr + g;
        const __half* q0 = qkv + (size_t)r0 * (3 * D_DIM) + h * HD_DIM;
        const __half* q8 = q0 + 8 * (3 * D_DIM);
        float2 raw[4][4];
        #pragma unroll
        for (int dc = 0; dc < 4; dc++) {
            const int c = dc * 16 + 2 * t;
            raw[dc][0] = __half22float2(*(const __half2*)(q0 + c));
            raw[dc][1] = __half22float2(*(const __half2*)(q8 + c));
            raw[dc][2] = __half22float2(*(const __half2*)(q0 + c + 8));
            raw[dc][3] = __half22float2(*(const __half2*)(q8 + c + 8));
        }
        #pragma unroll
        for (int dc = 0; dc < 4; dc++) {
            const float sgn = (dc < 2) ? -1.f : 1.f;
            #pragma unroll
            for (int j = 0; j < 4; j++) {
                const int row = (j & 1) ? (r0 + 8) : r0;
                const int d = dc * 16 + 2 * t + ((j >> 1) ? 8 : 0);
                float2 cv = *(const float2*)(cosp + row * 64 + d);
                float2 sv = *(const float2*)(sinp + row * 64 + d);
                float2 pp = raw[dc ^ 2][j];
                qf[dc][j] = h2pack(raw[dc][j].x * cv.x + sgn * pp.x * sv.x,
                                   raw[dc][j].y * cv.y + sgn * pp.y * sv.y);
            }
        }
    }

    float m0 = -3.4e38f, m1 = -3.4e38f, l0 = 0.f, l1 = 0.f;
    float out[8][4];
    #pragma unroll
    for (int n = 0; n < 8; n++)
        #pragma unroll
        for (int e = 0; e < 4; e++) out[n][e] = 0.f;

    const int kr = tid >> 3;
    const int kc8 = (tid & 7) * 8;
    auto load_chunk = [&](int buf, int kb) {
        const __half* base = qkv + (size_t)(kb + kr) * (3 * D_DIM) + h * HD_DIM + kc8;
        cp16(&Kh[buf][kr][kc8], base + D_DIM);
        cp16(&Vh[buf][kr][kc8], base + 2 * D_DIM);
        cp_commit();
    };

    load_chunk(0, start);

    const int nch = len >> 5;
    for (int c = 0; c < nch; c++) {
        const int buf = c & 1;
        asm volatile("cp.async.wait_group 0;\n");
        __syncthreads();
        if (c + 1 < nch) load_chunk(buf ^ 1, start + (c + 1) * 32);

        // S = Q @ K^T
        float sacc[4][4];
        #pragma unroll
        for (int j = 0; j < 4; j++)
            #pragma unroll
            for (int e = 0; e < 4; e++) sacc[j][e] = 0.f;
        #pragma unroll
        for (int dc = 0; dc < 4; dc++) {
            #pragma unroll
            for (int kh = 0; kh < 2; kh++) {
                uint32_t r[4];
                ldsm_x4(r, &Kh[buf][kh * 16 + a_row][dc * 16 + a_chk]);
                mma_f16_2(sacc[kh * 2],     qf[dc][0], qf[dc][1], qf[dc][2], qf[dc][3],
                          r[0], r[2]);
                mma_f16_2(sacc[kh * 2 + 1], qf[dc][0], qf[dc][1], qf[dc][2], qf[dc][3],
                          r[1], r[3]);
            }
        }
        #pragma unroll
        for (int j = 0; j < 4; j++)
            #pragma unroll
            for (int e = 0; e < 4; e++) sacc[j][e] *= 0.125f;

        // online softmax
        float ml0 = -3.4e38f, ml1 = -3.4e38f;
        #pragma unroll
        for (int j = 0; j < 4; j++) {
            ml0 = fmaxf(ml0, fmaxf(sacc[j][0], sacc[j][1]));
            ml1 = fmaxf(ml1, fmaxf(sacc[j][2], sacc[j][3]));
        }
        ml0 = fmaxf(ml0, __shfl_xor_sync(0xffffffffu, ml0, 1));
        ml0 = fmaxf(ml0, __shfl_xor_sync(0xffffffffu, ml0, 2));
        ml1 = fmaxf(ml1, __shfl_xor_sync(0xffffffffu, ml1, 1));
        ml1 = fmaxf(ml1, __shfl_xor_sync(0xffffffffu, ml1, 2));
        const float mn0 = fmaxf(m0, ml0);
        const float mn1 = fmaxf(m1, ml1);
        const float f0 = __expf(m0 - mn0);
        const float f1 = __expf(m1 - mn1);

        uint32_t pa[2][4];
        float ll0 = 0.f, ll1 = 0.f;
        #pragma unroll
        for (int j = 0; j < 4; j++) {
            float p0 = __expf(sacc[j][0] - mn0);
            float p1 = __expf(sacc[j][1] - mn0);
            float p2 = __expf(sacc[j][2] - mn1);
            float p3 = __expf(sacc[j][3] - mn1);
            ll0 += p0 + p1; ll1 += p2 + p3;
            pa[j >> 1][(j & 1) * 2]     = h2pack(p0, p1);
            pa[j >> 1][(j & 1) * 2 + 1] = h2pack(p2, p3);
        }
        ll0 += __shfl_xor_sync(0xffffffffu, ll0, 1);
        ll0 += __shfl_xor_sync(0xffffffffu, ll0, 2);
        ll1 += __shfl_xor_sync(0xffffffffu, ll1, 1);
        ll1 += __shfl_xor_sync(0xffffffffu, ll1, 2);
        l0 = l0 * f0 + ll0;
        l1 = l1 * f1 + ll1;
        m0 = mn0; m1 = mn1;
        #pragma unroll
        for (int n = 0; n < 8; n++) {
            out[n][0] *= f0; out[n][1] *= f0;
            out[n][2] *= f1; out[n][3] *= f1;
        }

        // out += P @ V
        #pragma unroll
        for (int kc = 0; kc < 2; kc++) {
            #pragma unroll
            for (int p = 0; p < 4; p++) {
                uint32_t r[4];
                ldsm_x4_t(r, &Vh[buf][kc * 16 + a_row][p * 16 + a_chk]);
                mma_f16(out[p * 2], pa[kc], r);
                mma_f16_2(out[p * 2 + 1], pa[kc][0], pa[kc][1], pa[kc][2], pa[kc][3],
                          r[2], r[3]);
            }
        }
    }

    const float i0 = 1.f / l0;
    const float i1 = 1.f / l1;
    __half* o0 = ao + (size_t)(s0 + pr + g) * D_DIM + h * HD_DIM;
    __half* o8 = o0 + 8 * D_DIM;
    #pragma unroll
    for (int n = 0; n < 8; n++) {
        *(uint32_t*)(o0 + 8 * n + 2 * t) = h2pack(out[n][0] * i0, out[n][1] * i0);
        *(uint32_t*)(o8 + 8 * n + 2 * t) = h2pack(out[n][2] * i1, out[n][3] * i1);
    }
}

// ---------------- driver ----------------
extern "C" void kernel_launch(void* const* d_in, const int* in_sizes, int n_in,
                              void* d_out, int out_size) {
    const float* hidden = (const float*)d_in[0];
    const int*   cu     = (const int*)d_in[1];
    const float* cosp   = (const float*)d_in[2];
    const float* sinp   = (const float*)d_in[3];
    const float* ln1_g  = (const float*)d_in[4];
    const float* ln1_b  = (const float*)d_in[5];
    const float* qkv_w  = (const float*)d_in[6];
    const float* qkv_b  = (const float*)d_in[7];
    const float* proj_w = (const float*)d_in[8];
    const float* proj_b = (const float*)d_in[9];
    const float* ln2_g  = (const float*)d_in[10];
    const float* ln2_b  = (const float*)d_in[11];
    const float* fc1_w  = (const float*)d_in[12];
    const float* fc1_b  = (const float*)d_in[13];
    const float* fc2_w  = (const float*)d_in[14];
    const float* fc2_b  = (const float*)d_in[15];

    float* x = (float*)d_out;

    __half *h, *qkv, *ao, *ff, *wq, *wp, *w1, *w2;
    cudaGetSymbolAddress((void**)&h,   g_h);
    cudaGetSymbolAddress((void**)&qkv, g_qkv);
    cudaGetSymbolAddress((void**)&ao,  g_ao);
    cudaGetSymbolAddress((void**)&ff,  g_ff);
    cudaGetSymbolAddress((void**)&wq,  g_wq);
    cudaGetSymbolAddress((void**)&wp,  g_wp);
    cudaGetSymbolAddress((void**)&w1,  g_w1);
    cudaGetSymbolAddress((void**)&w2,  g_w2);

    cudaFuncSetAttribute(gemm_f16_kernel<0, __half>,
                         cudaFuncAttributeMaxDynamicSharedMemorySize, G3_SMEM_BYTES);
    cudaFuncSetAttribute(gemm_f16_kernel<1, __half>,
                         cudaFuncAttributeMaxDynamicSharedMemorySize, G3_SMEM_BYTES);
    cudaFuncSetAttribute(gemm_f16_kernel<2, float>,
                         cudaFuncAttributeMaxDynamicSharedMemorySize, G3_SMEM_BYTES);

    // fused weight conversion (fp32 -> fp16), 16 elems/thread
    {
        const int n0 = DEPTH * D_DIM * 3 * D_DIM / 16;
        const int n1 = DEPTH * D_DIM * D_DIM / 16;
        const int n2 = DEPTH * D_DIM * FF_DIM / 16;
        const int n3 = DEPTH * FF_DIM * D_DIM / 16;
        const int total = n0 + n1 + n2 + n3;
        f2h_all_kernel<<<(total + 255) / 256, 256>>>(
            qkv_w, wq, n0, proj_w, wp, n1, fc1_w, w1, n2, fc2_w, w2, n3);
    }

    cudaMemcpyAsync(x, hidden, (size_t)S_LEN * D_DIM * sizeof(float),
                    cudaMemcpyDeviceToDevice);

    for (int i = 0; i < DEPTH; i++) {
        const __half* wqi = wq + (size_t)i * D_DIM * 3 * D_DIM;
        const float*  qb  = qkv_b  + (size_t)i * 3 * D_DIM;
        const __half* wpi = wp + (size_t)i * D_DIM * D_DIM;
        const float*  pb  = proj_b + (size_t)i * D_DIM;
        const __half* w1i = w1 + (size_t)i * D_DIM * FF_DIM;
        const float*  f1b = fc1_b  + (size_t)i * FF_DIM;
        const __half* w2i = w2 + (size_t)i * FF_DIM * D_DIM;
        const float*  f2b = fc2_b  + (size_t)i * D_DIM;

        ln_kernel<<<S_LEN / 8, 256>>>(x, ln1_g + (size_t)i * D_DIM,
                                      ln1_b + (size_t)i * D_DIM, h);

        {   // qkv = h @ qkv_w + qkv_b  (half out)
            dim3 grid(3 * D_DIM / 128, S_LEN / 128);
            gemm_f16_kernel<0, __half><<<grid, 256, G3_SMEM_BYTES>>>(
                h, wqi, qb, nullptr, qkv, S_LEN, 3 * D_DIM, D_DIM);
        }

        {   // RoPE on K only (Q fused into attention)
            int total = S_LEN * H_NUM * 16;
            rope_k_kernel<<<(total + 255) / 256, 256>>>(qkv, cosp, sinp);
        }

        {   // attention -> half ao
            dim3 grid(S_LEN / 128, H_NUM);
            attn_kernel<<<grid, 256>>>(qkv, cu, cosp, sinp, ao);
        }

        {   // x += ao @ proj_w + proj_b  (fp32 out)
            dim3 grid(D_DIM / 128, S_LEN / 128);
            gemm_f16_kernel<2, float><<<grid, 256, G3_SMEM_BYTES>>>(
                ao, wpi, pb, x, x, S_LEN, D_DIM, D_DIM);
        }

        ln_kernel<<<S_LEN / 8, 256>>>(x, ln2_g + (size_t)i * D_DIM,
                                      ln2_b + (size_t)i * D_DIM, h);

        {   // ff = gelu(h @ fc1_w + fc1_b)  (half out)
            dim3 grid(FF_DIM / 128, S_LEN / 128);
            gemm_f16_kernel<1, __half><<<grid, 256, G3_SMEM_BYTES>>>(
                h, w1i, f1b, nullptr, ff, S_LEN, FF_DIM, D_DIM);
        }

        {   // x += ff @ fc2_w + fc2_b  (fp32 out)
            dim3 grid(D_DIM / 128, S_LEN / 128);
            gemm_f16_kernel<2, float><<<grid, 256, G3_SMEM_BYTES>>>(
                ff, w2i, f2b, x, x, S_LEN, D_DIM, FF_DIM);
        }
    }
}

// round 16
// speedup vs baseline: 1.0853x; 1.0257x over previous
#include <cuda_runtime.h>
#include <cuda_fp16.h>
#include <math.h>
#include <stdint.h>

#define S_LEN 2048
#define D_DIM 1024
#define H_NUM 16
#define HD_DIM 64
#define FF_DIM 4096
#define DEPTH 2
#define NSEG 4
#define EPS 1e-6f

// ---------------- scratch (device globals; allocation-free) ----------------
__device__ __half g_h  [S_LEN * D_DIM];          // LN output (half)
__device__ __half g_qkv[S_LEN * 3 * D_DIM];      // qkv projection (half)
__device__ __half g_ao [S_LEN * D_DIM];          // attention output (half)
__device__ __half g_ff [S_LEN * FF_DIM];         // fc1+gelu output (half)
__device__ float  g_part[2 * S_LEN * D_DIM];     // split-K partials (fp32)
// half weights [K, N] row-major
__device__ __half g_wq[DEPTH * D_DIM * 3 * D_DIM];
__device__ __half g_wp[DEPTH * D_DIM * D_DIM];
__device__ __half g_w1[DEPTH * D_DIM * FF_DIM];
__device__ __half g_w2[DEPTH * FF_DIM * D_DIM];

// ---------------- helpers ----------------
__device__ __forceinline__ void mma_f16(float* d, const uint32_t* a, const uint32_t* b) {
    asm volatile(
        "mma.sync.aligned.m16n8k16.row.col.f32.f16.f16.f32 "
        "{%0,%1,%2,%3}, {%4,%5,%6,%7}, {%8,%9}, {%0,%1,%2,%3};\n"
        : "+f"(d[0]), "+f"(d[1]), "+f"(d[2]), "+f"(d[3])
        : "r"(a[0]), "r"(a[1]), "r"(a[2]), "r"(a[3]), "r"(b[0]), "r"(b[1]));
}
__device__ __forceinline__ void mma_f16_2(float* d,
                                          uint32_t a0, uint32_t a1, uint32_t a2, uint32_t a3,
                                          uint32_t b0, uint32_t b1) {
    asm volatile(
        "mma.sync.aligned.m16n8k16.row.col.f32.f16.f16.f32 "
        "{%0,%1,%2,%3}, {%4,%5,%6,%7}, {%8,%9}, {%0,%1,%2,%3};\n"
        : "+f"(d[0]), "+f"(d[1]), "+f"(d[2]), "+f"(d[3])
        : "r"(a0), "r"(a1), "r"(a2), "r"(a3), "r"(b0), "r"(b1));
}
__device__ __forceinline__ void ldsm_x4(uint32_t* r, const void* p) {
    uint32_t a = (uint32_t)__cvta_generic_to_shared(p);
    asm volatile("ldmatrix.sync.aligned.m8n8.x4.shared.b16 {%0,%1,%2,%3}, [%4];"
                 : "=r"(r[0]), "=r"(r[1]), "=r"(r[2]), "=r"(r[3]) : "r"(a));
}
__device__ __forceinline__ void ldsm_x4_t(uint32_t* r, const void* p) {
    uint32_t a = (uint32_t)__cvta_generic_to_shared(p);
    asm volatile("ldmatrix.sync.aligned.m8n8.x4.trans.shared.b16 {%0,%1,%2,%3}, [%4];"
                 : "=r"(r[0]), "=r"(r[1]), "=r"(r[2]), "=r"(r[3]) : "r"(a));
}
__device__ __forceinline__ void cp16(void* dst, const void* src) {
    uint32_t d = (uint32_t)__cvta_generic_to_shared(dst);
    asm volatile("cp.async.cg.shared.global [%0], [%1], 16;\n" :: "r"(d), "l"(src));
}
__device__ __forceinline__ void cp_commit() {
    asm volatile("cp.async.commit_group;\n");
}
__device__ __forceinline__ uint32_t h2pack(float a, float b) {
    __half2 h = __floats2half2_rn(a, b);
    return *(uint32_t*)&h;
}

// ------------- fused fp32 -> fp16 conversion, 16 elems/thread --------------
__device__ __forceinline__ void cvt16(const float4* s, uint4* d, int j) {
    float4 a = s[4 * j], b = s[4 * j + 1], c = s[4 * j + 2], e = s[4 * j + 3];
    uint4 o0, o1;
    o0.x = h2pack(a.x, a.y); o0.y = h2pack(a.z, a.w);
    o0.z = h2pack(b.x, b.y); o0.w = h2pack(b.z, b.w);
    o1.x = h2pack(c.x, c.y); o1.y = h2pack(c.z, c.w);
    o1.z = h2pack(e.x, e.y); o1.w = h2pack(e.z, e.w);
    d[2 * j] = o0; d[2 * j + 1] = o1;
}
__global__ void f2h_all_kernel(const float* w0, __half* o0, int n0,   // in 16-elem units
                               const float* w1, __half* o1, int n1,
                               const float* w2, __half* o2, int n2,
                               const float* w3, __half* o3, int n3) {
    int i = blockIdx.x * blockDim.x + threadIdx.x;
    if (i < n0) { cvt16((const float4*)w0, (uint4*)o0, i); return; }
    i -= n0;
    if (i < n1) { cvt16((const float4*)w1, (uint4*)o1, i); return; }
    i -= n1;
    if (i < n2) { cvt16((const float4*)w2, (uint4*)o2, i); return; }
    i -= n2;
    if (i < n3) { cvt16((const float4*)w3, (uint4*)o3, i); }
}

// ---------------- LayerNorm: one WARP per row, half output -----------------
__global__ __launch_bounds__(256)
void ln_kernel(const float* __restrict__ x,
               const float* __restrict__ g,
               const float* __restrict__ b,
               __half* __restrict__ out) {
    const int lane = threadIdx.x & 31;
    const int row  = blockIdx.x * 8 + (threadIdx.x >> 5);
    const float* xr = x + (size_t)row * D_DIM;

    float4 v[8];
    float s = 0.f;
    #pragma unroll
    for (int i = 0; i < 8; i++) {
        v[i] = *(const float4*)(xr + i * 128 + lane * 4);
        s += v[i].x + v[i].y + v[i].z + v[i].w;
    }
    #pragma unroll
    for (int o = 16; o > 0; o >>= 1) s += __shfl_xor_sync(0xffffffffu, s, o);
    const float mean = s * (1.f / D_DIM);

    float var = 0.f;
    #pragma unroll
    for (int i = 0; i < 8; i++) {
        float dx = v[i].x - mean, dy = v[i].y - mean;
        float dz = v[i].z - mean, dw = v[i].w - mean;
        var += dx * dx + dy * dy + dz * dz + dw * dw;
    }
    #pragma unroll
    for (int o = 16; o > 0; o >>= 1) var += __shfl_xor_sync(0xffffffffu, var, o);
    const float rstd = rsqrtf(var * (1.f / D_DIM) + EPS);

    __half* orow = out + (size_t)row * D_DIM;
    #pragma unroll
    for (int i = 0; i < 8; i++) {
        const int col = i * 128 + lane * 4;
        float4 gv = *(const float4*)(g + col);
        float4 bv = *(const float4*)(b + col);
        uint2 o;
        o.x = h2pack((v[i].x - mean) * rstd * gv.x + bv.x,
                     (v[i].y - mean) * rstd * gv.y + bv.y);
        o.y = h2pack((v[i].z - mean) * rstd * gv.z + bv.z,
                     (v[i].w - mean) * rstd * gv.w + bv.w);
        *(uint2*)(orow + col) = o;
    }
}

// ------- FP16 GEMM: 128x128 tile, BK=64, 2-stage cp.async ------
// Kstride = A row stride (full K); K = per-split depth; blockIdx.z = K-split.
// EPI: 0 = bias (half C), 1 = bias + exact GELU (half C),
//      2 = bias + resid (float C), 3 = split-K partial (float, no bias)
#define G3_AS_HALFS (2 * 128 * 72)
#define G3_SMEM_BYTES ((2 * 128 * 72 + 2 * 64 * 136) * 2)   // 71680
template<int EPI, typename CT>
__global__ __launch_bounds__(256)
void gemm_f16_kernel(const __half* __restrict__ A,
                     const __half* __restrict__ B,
                     const float* __restrict__ bias,
                     const float* __restrict__ resid,
                     CT* __restrict__ C,
                     int M, int N, int K, int Kstride) {
    extern __shared__ __half gsm[];
    __half (*As)[128][72] = (__half(*)[128][72])gsm;
    __half (*Bs)[64][136] = (__half(*)[64][136])(gsm + G3_AS_HALFS);

    const int tid  = threadIdx.x;
    const int lane = tid & 31;
    const int wid  = tid >> 5;
    const int warp_m = wid & 1;
    const int warp_n = wid >> 1;
    const int g = lane >> 2;
    const int t = lane & 3;

    const int bx = blockIdx.x;
    const int by = blockIdx.y;
    const int kbase = blockIdx.z * K;

    const __half* Ag = A + (size_t)by * 128 * Kstride + kbase;
    const __half* Bg = B + (size_t)bx * 128 + (size_t)kbase * N;

    float acc[4][4][4];
    #pragma unroll
    for (int mi = 0; mi < 4; mi++)
        #pragma unroll
        for (int ni = 0; ni < 4; ni++)
            #pragma unroll
            for (int e = 0; e < 4; e++) acc[mi][ni][e] = 0.f;

    const int NIT = K >> 6;    // BK = 64

    auto load_stage = [&](int st, int k0) {
        #pragma unroll
        for (int i = 0; i < 4; i++) {
            int id = tid + 256 * i;
            int r = id >> 3, c = (id & 7) * 8;
            cp16(&As[st][r][c], Ag + (size_t)r * Kstride + k0 + c);
        }
        #pragma unroll
        for (int i = 0; i < 4; i++) {
            int id = tid + 256 * i;
            int r = id >> 4, c = (id & 15) * 8;
            cp16(&Bs[st][r][c], Bg + (size_t)(k0 + r) * N + c);
        }
        cp_commit();
    };

    load_stage(0, 0);

    const int a_row = lane & 15;
    const int a_chk = (lane >> 4) * 8;

    #pragma unroll 1
    for (int it = 0; it < NIT; it++) {
        const int buf = it & 1;
        asm volatile("cp.async.wait_group 0;\n");
        __syncthreads();
        if (it + 1 < NIT) load_stage(buf ^ 1, (it + 1) << 6);

        #pragma unroll
        for (int ks = 0; ks < 4; ks++) {
            uint32_t af[4][4], bf[4][2];
            #pragma unroll
            for (int mi = 0; mi < 4; mi++) {
                int row = warp_m * 64 + mi * 16 + a_row;
                ldsm_x4(af[mi], &As[buf][row][ks * 16 + a_chk]);
            }
            #pragma unroll
            for (int p = 0; p < 2; p++) {
                uint32_t r[4];
                int krow = ks * 16 + a_row;
                int ncol = warp_n * 32 + p * 16 + a_chk;
                ldsm_x4_t(r, &Bs[buf][krow][ncol]);
                bf[p * 2][0] = r[0]; bf[p * 2][1] = r[1];
                bf[p * 2 + 1][0] = r[2]; bf[p * 2 + 1][1] = r[3];
            }
            #pragma unroll
            for (int mi = 0; mi < 4; mi++)
                #pragma unroll
                for (int ni = 0; ni < 4; ni++)
                    mma_f16(acc[mi][ni], af[mi], bf[ni]);
        }
    }

    float* Cp = (float*)C;
    if (EPI == 3) Cp = (float*)C + (size_t)blockIdx.z * M * N;

    #pragma unroll
    for (int mi = 0; mi < 4; mi++) {
        const int row0 = by * 128 + warp_m * 64 + mi * 16 + g;
        #pragma unroll
        for (int ni = 0; ni < 4; ni++) {
            const int col = bx * 128 + warp_n * 32 + (ni >> 1) * 16 + (ni & 1) * 8 + 2 * t;
            #pragma unroll
            for (int half_ = 0; half_ < 2; half_++) {
                const int r = row0 + half_ * 8;
                if (EPI == 3) {
                    *(float2*)(Cp + (size_t)r * N + col) =
                        make_float2(acc[mi][ni][half_ * 2], acc[mi][ni][half_ * 2 + 1]);
                    continue;
                }
                float v0 = acc[mi][ni][half_ * 2]     + bias[col];
                float v1 = acc[mi][ni][half_ * 2 + 1] + bias[col + 1];
                if (EPI == 1) {
                    v0 = 0.5f * v0 * (1.f + erff(v0 * 0.70710678118654752f));
                    v1 = 0.5f * v1 * (1.f + erff(v1 * 0.70710678118654752f));
                } else if (EPI == 2) {
                    float2 rr = *(const float2*)(resid + (size_t)r * N + col);
                    v0 += rr.x; v1 += rr.y;
                }
                if (sizeof(CT) == 2) {
                    *(uint32_t*)((__half*)C + (size_t)r * N + col) = h2pack(v0, v1);
                } else {
                    *(float2*)((float*)C + (size_t)r * N + col) = make_float2(v0, v1);
                }
            }
        }
    }
}

// -------- split-K reduce: out = p0 + p1 + bias + resid (all fp32) ----------
__global__ void splitk_reduce_kernel(const float* __restrict__ part,
                                     const float* __restrict__ bias,
                                     const float* __restrict__ resid,
                                     float* __restrict__ out) {
    int i = blockIdx.x * blockDim.x + threadIdx.x;   // float4 index
    if (i >= S_LEN * D_DIM / 4) return;
    float4 a = ((const float4*)part)[i];
    float4 b = ((const float4*)(part + (size_t)S_LEN * D_DIM))[i];
    float4 r = ((const float4*)resid)[i];
    float4 bi = *(const float4*)(bias + ((i * 4) & (D_DIM - 1)));
    float4 o;
    o.x = a.x + b.x + bi.x + r.x;
    o.y = a.y + b.y + bi.y + r.y;
    o.z = a.z + b.z + bi.z + r.z;
    o.w = a.w + b.w + bi.w + r.w;
    ((float4*)out)[i] = o;
}

// ---------------- RoPE on K slice only, 4 dims/thread ----------------
__global__ void rope_k_kernel(__half* __restrict__ qkv,
                              const float* __restrict__ cosp,
                              const float* __restrict__ sinp) {
    int idx = blockIdx.x * blockDim.x + threadIdx.x;  // S*H*8
    if (idx >= S_LEN * H_NUM * 8) return;
    const int d4 = (idx & 7) * 4;
    const int h = (idx >> 3) & (H_NUM - 1);
    const int s = idx >> 7;

    const float4 c1 = *(const float4*)(cosp + s * 64 + d4);
    const float4 c2 = *(const float4*)(cosp + s * 64 + d4 + 32);
    const float4 s1 = *(const float4*)(sinp + s * 64 + d4);
    const float4 s2 = *(const float4*)(sinp + s * 64 + d4 + 32);

    __half* p = qkv + (size_t)s * (3 * D_DIM) + D_DIM + h * HD_DIM + d4;
    __half2 a0 = *(__half2*)p,        a1 = *(__half2*)(p + 2);
    __half2 b0 = *(__half2*)(p + 32), b1 = *(__half2*)(p + 34);
    float2 af0 = __half22float2(a0), af1 = __half22float2(a1);
    float2 bf0 = __half22float2(b0), bf1 = __half22float2(b1);
    uint2 lo, hi;
    lo.x = h2pack(af0.x * c1.x - bf0.x * s1.x, af0.y * c1.y - bf0.y * s1.y);
    lo.y = h2pack(af1.x * c1.z - bf1.x * s1.z, af1.y * c1.w - bf1.y * s1.w);
    hi.x = h2pack(bf0.x * c2.x + af0.x * s2.x, bf0.y * c2.y + af0.y * s2.y);
    hi.y = h2pack(bf1.x * c2.z + af1.x * s2.z, bf1.y * c2.w + af1.y * s2.w);
    *(uint2*)p = lo;
    *(uint2*)(p + 32) = hi;
}

// ---- fp16 flash attention, 64-key double-buffered chunks; Q-RoPE fused ----
__global__ __launch_bounds__(256)
void attn_kernel(const __half* __restrict__ qkv,
                 const int* __restrict__ cu,
                 const float* __restrict__ cosp,
                 const float* __restrict__ sinp,
                 __half* __restrict__ ao) {
    const int h  = blockIdx.y;
    const int s0 = blockIdx.x * 128;
    const int tid  = threadIdx.x;
    const int lane = tid & 31;
    const int wid  = tid >> 5;
    const int g = lane >> 2;
    const int t = lane & 3;
    const int a_row = lane & 15;
    const int a_chk = (lane >> 4) * 8;

    __shared__ __half Kh[2][64][72];
    __shared__ __half Vh[2][64][72];

    int start = 0, len = S_LEN;
    #pragma unroll
    for (int i = 0; i < NSEG; i++) {
        int a = cu[i], b = cu[i + 1];
        if (s0 >= a && s0 < b) { start = a; len = b - a; }
    }

    const int pr = wid * 16;

    // Q frags with fused RoPE (thread holds both rotate_half partners: dc and dc^2)
    uint32_t qf[4][4];
    {
        const int r0 = s0 + pr + g;
        const __half* q0 = qkv + (size_t)r0 * (3 * D_DIM) + h * HD_DIM;
        const __half* q8 = q0 + 8 * (3 * D_DIM);
        float2 raw[4][4];
        #pragma unroll
        for (int dc = 0; dc < 4; dc++) {
            const int c = dc * 16 + 2 * t;
            raw[dc][0] = __half22float2(*(const __half2*)(q0 + c));
            raw[dc][1] = __half22float2(*(const __half2*)(q8 + c));
            raw[dc][2] = __half22float2(*(const __half2*)(q0 + c + 8));
            raw[dc][3] = __half22float2(*(const __half2*)(q8 + c + 8));
        }
        #pragma unroll
        for (int dc = 0; dc < 4; dc++) {
            const float sgn = (dc < 2) ? -1.f : 1.f;
            #pragma unroll
            for (int j = 0; j < 4; j++) {
                const int row = (j & 1) ? (r0 + 8) : r0;
                const int d = dc * 16 + 2 * t + ((j >> 1) ? 8 : 0);
                float2 cv = *(const float2*)(cosp + row * 64 + d);
                float2 sv = *(const float2*)(sinp + row * 64 + d);
                float2 pp = raw[dc ^ 2][j];
                qf[dc][j] = h2pack(raw[dc][j].x * cv.x + sgn * pp.x * sv.x,
                                   raw[dc][j].y * cv.y + sgn * pp.y * sv.y);
            }
        }
    }

    float m0 = -3.4e38f, m1 = -3.4e38f, l0 = 0.f, l1 = 0.f;
    float out[8][4];
    #pragma unroll
    for (int n = 0; n < 8; n++)
        #pragma unroll
        for (int e = 0; e < 4; e++) out[n][e] = 0.f;

    const int kr = tid >> 3;         // 0..31
    const int kc8 = (tid & 7) * 8;
    auto load_chunk = [&](int buf, int kb) {
        #pragma unroll
        for (int rr = 0; rr < 2; rr++) {
            const __half* base = qkv + (size_t)(kb + kr + rr * 32) * (3 * D_DIM)
                               + h * HD_DIM + kc8;
            cp16(&Kh[buf][kr + rr * 32][kc8], base + D_DIM);
            cp16(&Vh[buf][kr + rr * 32][kc8], base + 2 * D_DIM);
        }
        cp_commit();
    };

    load_chunk(0, start);

    const int nch = len >> 6;       // 64-key chunks
    for (int c = 0; c < nch; c++) {
        const int buf = c & 1;
        asm volatile("cp.async.wait_group 0;\n");
        __syncthreads();
        if (c + 1 < nch) load_chunk(buf ^ 1, start + (c + 1) * 64);

        // S = Q @ K^T  (64 keys)
        float sacc[8][4];
        #pragma unroll
        for (int j = 0; j < 8; j++)
            #pragma unroll
            for (int e = 0; e < 4; e++) sacc[j][e] = 0.f;
        #pragma unroll
        for (int dc = 0; dc < 4; dc++) {
            #pragma unroll
            for (int kh = 0; kh < 4; kh++) {
                uint32_t r[4];
                ldsm_x4(r, &Kh[buf][kh * 16 + a_row][dc * 16 + a_chk]);
                mma_f16_2(sacc[kh * 2],     qf[dc][0], qf[dc][1], qf[dc][2], qf[dc][3],
                          r[0], r[2]);
                mma_f16_2(sacc[kh * 2 + 1], qf[dc][0], qf[dc][1], qf[dc][2], qf[dc][3],
                          r[1], r[3]);
            }
        }
        #pragma unroll
        for (int j = 0; j < 8; j++)
            #pragma unroll
            for (int e = 0; e < 4; e++) sacc[j][e] *= 0.125f;

        // online softmax
        float ml0 = -3.4e38f, ml1 = -3.4e38f;
        #pragma unroll
        for (int j = 0; j < 8; j++) {
            ml0 = fmaxf(ml0, fmaxf(sacc[j][0], sacc[j][1]));
            ml1 = fmaxf(ml1, fmaxf(sacc[j][2], sacc[j][3]));
        }
        ml0 = fmaxf(ml0, __shfl_xor_sync(0xffffffffu, ml0, 1));
        ml0 = fmaxf(ml0, __shfl_xor_sync(0xffffffffu, ml0, 2));
        ml1 = fmaxf(ml1, __shfl_xor_sync(0xffffffffu, ml1, 1));
        ml1 = fmaxf(ml1, __shfl_xor_sync(0xffffffffu, ml1, 2));
        const float mn0 = fmaxf(m0, ml0);
        const float mn1 = fmaxf(m1, ml1);
        const float f0 = __expf(m0 - mn0);
        const float f1 = __expf(m1 - mn1);

        uint32_t pa[4][4];
        float ll0 = 0.f, ll1 = 0.f;
        #pragma unroll
        for (int j = 0; j < 8; j++) {
            float p0 = __expf(sacc[j][0] - mn0);
            float p1 = __expf(sacc[j][1] - mn0);
            float p2 = __expf(sacc[j][2] - mn1);
            float p3 = __expf(sacc[j][3] - mn1);
            ll0 += p0 + p1; ll1 += p2 + p3;
            pa[j >> 1][(j & 1) * 2]     = h2pack(p0, p1);
            pa[j >> 1][(j & 1) * 2 + 1] = h2pack(p2, p3);
        }
        ll0 += __shfl_xor_sync(0xffffffffu, ll0, 1);
        ll0 += __shfl_xor_sync(0xffffffffu, ll0, 2);
        ll1 += __shfl_xor_sync(0xffffffffu, ll1, 1);
        ll1 += __shfl_xor_sync(0xffffffffu, ll1, 2);
        l0 = l0 * f0 + ll0;
        l1 = l1 * f1 + ll1;
        m0 = mn0; m1 = mn1;
        #pragma unroll
        for (int n = 0; n < 8; n++) {
            out[n][0] *= f0; out[n][1] *= f0;
            out[n][2] *= f1; out[n][3] *= f1;
        }

        // out += P @ V
        #pragma unroll
        for (int kc = 0; kc < 4; kc++) {
            #pragma unroll
            for (int p = 0; p < 4; p++) {
                uint32_t r[4];
                ldsm_x4_t(r, &Vh[buf][kc * 16 + a_row][p * 16 + a_chk]);
                mma_f16(out[p * 2], pa[kc], r);
                mma_f16_2(out[p * 2 + 1], pa[kc][0], pa[kc][1], pa[kc][2], pa[kc][3],
                          r[2], r[3]);
            }
        }
    }

    const float i0 = 1.f / l0;
    const float i1 = 1.f / l1;
    __half* o0 = ao + (size_t)(s0 + pr + g) * D_DIM + h * HD_DIM;
    __half* o8 = o0 + 8 * D_DIM;
    #pragma unroll
    for (int n = 0; n < 8; n++) {
        *(uint32_t*)(o0 + 8 * n + 2 * t) = h2pack(out[n][0] * i0, out[n][1] * i0);
        *(uint32_t*)(o8 + 8 * n + 2 * t) = h2pack(out[n][2] * i1, out[n][3] * i1);
    }
}

// ---------------- driver ----------------
extern "C" void kernel_launch(void* const* d_in, const int* in_sizes, int n_in,
                              void* d_out, int out_size) {
    const float* hidden = (const float*)d_in[0];
    const int*   cu     = (const int*)d_in[1];
    const float* cosp   = (const float*)d_in[2];
    const float* sinp   = (const float*)d_in[3];
    const float* ln1_g  = (const float*)d_in[4];
    const float* ln1_b  = (const float*)d_in[5];
    const float* qkv_w  = (const float*)d_in[6];
    const float* qkv_b  = (const float*)d_in[7];
    const float* proj_w = (const float*)d_in[8];
    const float* proj_b = (const float*)d_in[9];
    const float* ln2_g  = (const float*)d_in[10];
    const float* ln2_b  = (const float*)d_in[11];
    const float* fc1_w  = (const float*)d_in[12];
    const float* fc1_b  = (const float*)d_in[13];
    const float* fc2_w  = (const float*)d_in[14];
    const float* fc2_b  = (const float*)d_in[15];

    float* x = (float*)d_out;

    __half *h, *qkv, *ao, *ff, *wq, *wp, *w1, *w2;
    float *part;
    cudaGetSymbolAddress((void**)&h,    g_h);
    cudaGetSymbolAddress((void**)&qkv,  g_qkv);
    cudaGetSymbolAddress((void**)&ao,   g_ao);
    cudaGetSymbolAddress((void**)&ff,   g_ff);
    cudaGetSymbolAddress((void**)&part, g_part);
    cudaGetSymbolAddress((void**)&wq,   g_wq);
    cudaGetSymbolAddress((void**)&wp,   g_wp);
    cudaGetSymbolAddress((void**)&w1,   g_w1);
    cudaGetSymbolAddress((void**)&w2,   g_w2);

    cudaFuncSetAttribute(gemm_f16_kernel<0, __half>,
                         cudaFuncAttributeMaxDynamicSharedMemorySize, G3_SMEM_BYTES);
    cudaFuncSetAttribute(gemm_f16_kernel<1, __half>,
                         cudaFuncAttributeMaxDynamicSharedMemorySize, G3_SMEM_BYTES);
    cudaFuncSetAttribute(gemm_f16_kernel<3, float>,
                         cudaFuncAttributeMaxDynamicSharedMemorySize, G3_SMEM_BYTES);

    // fused weight conversion (fp32 -> fp16), 16 elems/thread
    {
        const int n0 = DEPTH * D_DIM * 3 * D_DIM / 16;
        const int n1 = DEPTH * D_DIM * D_DIM / 16;
        const int n2 = DEPTH * D_DIM * FF_DIM / 16;
        const int n3 = DEPTH * FF_DIM * D_DIM / 16;
        const int total = n0 + n1 + n2 + n3;
        f2h_all_kernel<<<(total + 255) / 256, 256>>>(
            qkv_w, wq, n0, proj_w, wp, n1, fc1_w, w1, n2, fc2_w, w2, n3);
    }

    cudaMemcpyAsync(x, hidden, (size_t)S_LEN * D_DIM * sizeof(float),
                    cudaMemcpyDeviceToDevice);

    const int red_threads = S_LEN * D_DIM / 4;

    for (int i = 0; i < DEPTH; i++) {
        const __half* wqi = wq + (size_t)i * D_DIM * 3 * D_DIM;
        const float*  qb  = qkv_b  + (size_t)i * 3 * D_DIM;
        const __half* wpi = wp + (size_t)i * D_DIM * D_DIM;
        const float*  pb  = proj_b + (size_t)i * D_DIM;
        const __half* w1i = w1 + (size_t)i * D_DIM * FF_DIM;
        const float*  f1b = fc1_b  + (size_t)i * FF_DIM;
        const __half* w2i = w2 + (size_t)i * FF_DIM * D_DIM;
        const float*  f2b = fc2_b  + (size_t)i * D_DIM;

        ln_kernel<<<S_LEN / 8, 256>>>(x, ln1_g + (size_t)i * D_DIM,
                                      ln1_b + (size_t)i * D_DIM, h);

        {   // qkv = h @ qkv_w + qkv_b  (half out)
            dim3 grid(3 * D_DIM / 128, S_LEN / 128);
            gemm_f16_kernel<0, __half><<<grid, 256, G3_SMEM_BYTES>>>(
                h, wqi, qb, nullptr, qkv, S_LEN, 3 * D_DIM, D_DIM, D_DIM);
        }

        {   // RoPE on K only (Q fused into attention)
            int total = S_LEN * H_NUM * 8;
            rope_k_kernel<<<(total + 255) / 256, 256>>>(qkv, cosp, sinp);
        }

        {   // attention -> half ao
            dim3 grid(S_LEN / 128, H_NUM);
            attn_kernel<<<grid, 256>>>(qkv, cu, cosp, sinp, ao);
        }

        {   // proj: split-K2 partials then reduce into x
            dim3 grid(D_DIM / 128, S_LEN / 128, 2);
            gemm_f16_kernel<3, float><<<grid, 256, G3_SMEM_BYTES>>>(
                ao, wpi, nullptr, nullptr, part, S_LEN, D_DIM, D_DIM / 2, D_DIM);
            splitk_reduce_kernel<<<(red_threads + 255) / 256, 256>>>(part, pb, x, x);
        }

        ln_kernel<<<S_LEN / 8, 256>>>(x, ln2_g + (size_t)i * D_DIM,
                                      ln2_b + (size_t)i * D_DIM, h);

        {   // ff = gelu(h @ fc1_w + fc1_b)  (half out)
            dim3 grid(FF_DIM / 128, S_LEN / 128);
            gemm_f16_kernel<1, __half><<<grid, 256, G3_SMEM_BYTES>>>(
                h, w1i, f1b, nullptr, ff, S_LEN, FF_DIM, D_DIM, D_DIM);
        }

        {   // fc2: split-K2 partials then reduce into x
            dim3 grid(D_DIM / 128, S_LEN / 128, 2);
            gemm_f16_kernel<3, float><<<grid, 256, G3_SMEM_BYTES>>>(
                ff, w2i, nullptr, nullptr, part, S_LEN, D_DIM, FF_DIM / 2, FF_DIM);
            splitk_reduce_kernel<<<(red_threads + 255) / 256, 256>>>(part, f2b, x, x);
        }
    }
}

// round 17
// speedup vs baseline: 1.1094x; 1.0221x over previous
#include <cuda_runtime.h>
#include <cuda_fp16.h>
#include <math.h>
#include <stdint.h>

#define S_LEN 2048
#define D_DIM 1024
#define H_NUM 16
#define HD_DIM 64
#define FF_DIM 4096
#define DEPTH 2
#define NSEG 4
#define EPS 1e-6f

// ---------------- scratch (device globals; allocation-free) ----------------
__device__ __half g_h  [S_LEN * D_DIM];          // LN output (half)
__device__ __half g_qkv[S_LEN * 3 * D_DIM];      // qkv projection (half)
__device__ __half g_ao [S_LEN * D_DIM];          // attention output (half)
__device__ __half g_ff [S_LEN * FF_DIM];         // fc1+gelu output (half)
__device__ float  g_part[2 * S_LEN * D_DIM];     // split-K partials (fp32)
// half weights [K, N] row-major
__device__ __half g_wq[DEPTH * D_DIM * 3 * D_DIM];
__device__ __half g_wp[DEPTH * D_DIM * D_DIM];
__device__ __half g_w1[DEPTH * D_DIM * FF_DIM];
__device__ __half g_w2[DEPTH * FF_DIM * D_DIM];

// ---------------- helpers ----------------
__device__ __forceinline__ void mma_f16(float* d, const uint32_t* a, const uint32_t* b) {
    asm volatile(
        "mma.sync.aligned.m16n8k16.row.col.f32.f16.f16.f32 "
        "{%0,%1,%2,%3}, {%4,%5,%6,%7}, {%8,%9}, {%0,%1,%2,%3};\n"
        : "+f"(d[0]), "+f"(d[1]), "+f"(d[2]), "+f"(d[3])
        : "r"(a[0]), "r"(a[1]), "r"(a[2]), "r"(a[3]), "r"(b[0]), "r"(b[1]));
}
__device__ __forceinline__ void mma_f16_2(float* d,
                                          uint32_t a0, uint32_t a1, uint32_t a2, uint32_t a3,
                                          uint32_t b0, uint32_t b1) {
    asm volatile(
        "mma.sync.aligned.m16n8k16.row.col.f32.f16.f16.f32 "
        "{%0,%1,%2,%3}, {%4,%5,%6,%7}, {%8,%9}, {%0,%1,%2,%3};\n"
        : "+f"(d[0]), "+f"(d[1]), "+f"(d[2]), "+f"(d[3])
        : "r"(a0), "r"(a1), "r"(a2), "r"(a3), "r"(b0), "r"(b1));
}
__device__ __forceinline__ void ldsm_x4(uint32_t* r, const void* p) {
    uint32_t a = (uint32_t)__cvta_generic_to_shared(p);
    asm volatile("ldmatrix.sync.aligned.m8n8.x4.shared.b16 {%0,%1,%2,%3}, [%4];"
                 : "=r"(r[0]), "=r"(r[1]), "=r"(r[2]), "=r"(r[3]) : "r"(a));
}
__device__ __forceinline__ void ldsm_x4_t(uint32_t* r, const void* p) {
    uint32_t a = (uint32_t)__cvta_generic_to_shared(p);
    asm volatile("ldmatrix.sync.aligned.m8n8.x4.trans.shared.b16 {%0,%1,%2,%3}, [%4];"
                 : "=r"(r[0]), "=r"(r[1]), "=r"(r[2]), "=r"(r[3]) : "r"(a));
}
__device__ __forceinline__ void cp16(void* dst, const void* src) {
    uint32_t d = (uint32_t)__cvta_generic_to_shared(dst);
    asm volatile("cp.async.cg.shared.global [%0], [%1], 16;\n" :: "r"(d), "l"(src));
}
__device__ __forceinline__ void cp_commit() {
    asm volatile("cp.async.commit_group;\n");
}
__device__ __forceinline__ uint32_t h2pack(float a, float b) {
    __half2 h = __floats2half2_rn(a, b);
    return *(uint32_t*)&h;
}

// ------------- fused fp32 -> fp16 conversion, 16 elems/thread --------------
__device__ __forceinline__ void cvt16(const float4* s, uint4* d, int j) {
    float4 a = s[4 * j], b = s[4 * j + 1], c = s[4 * j + 2], e = s[4 * j + 3];
    uint4 o0, o1;
    o0.x = h2pack(a.x, a.y); o0.y = h2pack(a.z, a.w);
    o0.z = h2pack(b.x, b.y); o0.w = h2pack(b.z, b.w);
    o1.x = h2pack(c.x, c.y); o1.y = h2pack(c.z, c.w);
    o1.z = h2pack(e.x, e.y); o1.w = h2pack(e.z, e.w);
    d[2 * j] = o0; d[2 * j + 1] = o1;
}
__global__ void f2h_all_kernel(const float* w0, __half* o0, int n0,   // in 16-elem units
                               const float* w1, __half* o1, int n1,
                               const float* w2, __half* o2, int n2,
                               const float* w3, __half* o3, int n3) {
    int i = blockIdx.x * blockDim.x + threadIdx.x;
    if (i < n0) { cvt16((const float4*)w0, (uint4*)o0, i); return; }
    i -= n0;
    if (i < n1) { cvt16((const float4*)w1, (uint4*)o1, i); return; }
    i -= n1;
    if (i < n2) { cvt16((const float4*)w2, (uint4*)o2, i); return; }
    i -= n2;
    if (i < n3) { cvt16((const float4*)w3, (uint4*)o3, i); }
}

// ---------- LN core on register-resident row (warp-per-row) ----------
__device__ __forceinline__ void ln_write(const float4* v, const float* g,
                                         const float* b, __half* orow, int lane) {
    float s = 0.f;
    #pragma unroll
    for (int i = 0; i < 8; i++) s += v[i].x + v[i].y + v[i].z + v[i].w;
    #pragma unroll
    for (int o = 16; o > 0; o >>= 1) s += __shfl_xor_sync(0xffffffffu, s, o);
    const float mean = s * (1.f / D_DIM);

    float var = 0.f;
    #pragma unroll
    for (int i = 0; i < 8; i++) {
        float dx = v[i].x - mean, dy = v[i].y - mean;
        float dz = v[i].z - mean, dw = v[i].w - mean;
        var += dx * dx + dy * dy + dz * dz + dw * dw;
    }
    #pragma unroll
    for (int o = 16; o > 0; o >>= 1) var += __shfl_xor_sync(0xffffffffu, var, o);
    const float rstd = rsqrtf(var * (1.f / D_DIM) + EPS);

    #pragma unroll
    for (int i = 0; i < 8; i++) {
        const int col = i * 128 + lane * 4;
        float4 gv = *(const float4*)(g + col);
        float4 bv = *(const float4*)(b + col);
        uint2 o;
        o.x = h2pack((v[i].x - mean) * rstd * gv.x + bv.x,
                     (v[i].y - mean) * rstd * gv.y + bv.y);
        o.y = h2pack((v[i].z - mean) * rstd * gv.z + bv.z,
                     (v[i].w - mean) * rstd * gv.w + bv.w);
        *(uint2*)(orow + col) = o;
    }
}

// ---------------- LayerNorm only (x -> h) ----------------
__global__ __launch_bounds__(256)
void ln_kernel(const float* __restrict__ x,
               const float* __restrict__ g,
               const float* __restrict__ b,
               __half* __restrict__ out) {
    const int lane = threadIdx.x & 31;
    const int row  = blockIdx.x * 8 + (threadIdx.x >> 5);
    const float* xr = x + (size_t)row * D_DIM;
    float4 v[8];
    #pragma unroll
    for (int i = 0; i < 8; i++) v[i] = *(const float4*)(xr + i * 128 + lane * 4);
    ln_write(v, g, b, out + (size_t)row * D_DIM, lane);
}

// ------------- copy + LN: x = hidden; h = LN(hidden) -------------
__global__ __launch_bounds__(256)
void copy_ln_kernel(const float* __restrict__ src,
                    const float* __restrict__ g,
                    const float* __restrict__ b,
                    float* __restrict__ x,
                    __half* __restrict__ out) {
    const int lane = threadIdx.x & 31;
    const int row  = blockIdx.x * 8 + (threadIdx.x >> 5);
    const float* xr = src + (size_t)row * D_DIM;
    float* xo = x + (size_t)row * D_DIM;
    float4 v[8];
    #pragma unroll
    for (int i = 0; i < 8; i++) {
        v[i] = *(const float4*)(xr + i * 128 + lane * 4);
        *(float4*)(xo + i * 128 + lane * 4) = v[i];
    }
    ln_write(v, g, b, out + (size_t)row * D_DIM, lane);
}

// -- split-K reduce (+ optional fused LN): x = p0+p1+bias+resid; h = LN(x) --
template<int DO_LN>
__global__ __launch_bounds__(256)
void red_ln_kernel(const float* __restrict__ part,
                   const float* __restrict__ bias,
                   const float* __restrict__ resid,
                   float* __restrict__ x,
                   const float* __restrict__ g,
                   const float* __restrict__ b,
                   __half* __restrict__ out) {
    const int lane = threadIdx.x & 31;
    const int row  = blockIdx.x * 8 + (threadIdx.x >> 5);
    const size_t off = (size_t)row * D_DIM;
    const float* p0 = part + off;
    const float* p1 = part + (size_t)S_LEN * D_DIM + off;
    const float* rr = resid + off;
    float* xo = x + off;
    float4 v[8];
    #pragma unroll
    for (int i = 0; i < 8; i++) {
        const int col = i * 128 + lane * 4;
        float4 a = *(const float4*)(p0 + col);
        float4 c = *(const float4*)(p1 + col);
        float4 r = *(const float4*)(rr + col);
        float4 bi = *(const float4*)(bias + col);
        v[i].x = a.x + c.x + bi.x + r.x;
        v[i].y = a.y + c.y + bi.y + r.y;
        v[i].z = a.z + c.z + bi.z + r.z;
        v[i].w = a.w + c.w + bi.w + r.w;
        *(float4*)(xo + col) = v[i];
    }
    if (DO_LN) ln_write(v, g, b, out + off, lane);
}

// ------- FP16 GEMM: 128x128 tile, BK=64, 2-stage cp.async ------
// Kstride = A row stride (full K); K = per-split depth; blockIdx.z = K-split.
// EPI: 0 = bias (half C), 1 = bias + exact GELU (half C),
//      2 = bias + resid (float C), 3 = split-K partial (float, no bias)
#define G3_AS_HALFS (2 * 128 * 72)
#define G3_SMEM_BYTES ((2 * 128 * 72 + 2 * 64 * 136) * 2)   // 71680
template<int EPI, typename CT>
__global__ __launch_bounds__(256)
void gemm_f16_kernel(const __half* __restrict__ A,
                     const __half* __restrict__ B,
                     const float* __restrict__ bias,
                     const float* __restrict__ resid,
                     CT* __restrict__ C,
                     int M, int N, int K, int Kstride) {
    extern __shared__ __half gsm[];
    __half (*As)[128][72] = (__half(*)[128][72])gsm;
    __half (*Bs)[64][136] = (__half(*)[64][136])(gsm + G3_AS_HALFS);

    const int tid  = threadIdx.x;
    const int lane = tid & 31;
    const int wid  = tid >> 5;
    const int warp_m = wid & 1;
    const int warp_n = wid >> 1;
    const int g = lane >> 2;
    const int t = lane & 3;

    const int bx = blockIdx.x;
    const int by = blockIdx.y;
    const int kbase = blockIdx.z * K;

    const __half* Ag = A + (size_t)by * 128 * Kstride + kbase;
    const __half* Bg = B + (size_t)bx * 128 + (size_t)kbase * N;

    float acc[4][4][4];
    #pragma unroll
    for (int mi = 0; mi < 4; mi++)
        #pragma unroll
        for (int ni = 0; ni < 4; ni++)
            #pragma unroll
            for (int e = 0; e < 4; e++) acc[mi][ni][e] = 0.f;

    const int NIT = K >> 6;    // BK = 64

    auto load_stage = [&](int st, int k0) {
        #pragma unroll
        for (int i = 0; i < 4; i++) {
            int id = tid + 256 * i;
            int r = id >> 3, c = (id & 7) * 8;
            cp16(&As[st][r][c], Ag + (size_t)r * Kstride + k0 + c);
        }
        #pragma unroll
        for (int i = 0; i < 4; i++) {
            int id = tid + 256 * i;
            int r = id >> 4, c = (id & 15) * 8;
            cp16(&Bs[st][r][c], Bg + (size_t)(k0 + r) * N + c);
        }
        cp_commit();
    };

    load_stage(0, 0);

    const int a_row = lane & 15;
    const int a_chk = (lane >> 4) * 8;

    #pragma unroll 1
    for (int it = 0; it < NIT; it++) {
        const int buf = it & 1;
        asm volatile("cp.async.wait_group 0;\n");
        __syncthreads();
        if (it + 1 < NIT) load_stage(buf ^ 1, (it + 1) << 6);

        #pragma unroll
        for (int ks = 0; ks < 4; ks++) {
            uint32_t af[4][4], bf[4][2];
            #pragma unroll
            for (int mi = 0; mi < 4; mi++) {
                int row = warp_m * 64 + mi * 16 + a_row;
                ldsm_x4(af[mi], &As[buf][row][ks * 16 + a_chk]);
            }
            #pragma unroll
            for (int p = 0; p < 2; p++) {
                uint32_t r[4];
                int krow = ks * 16 + a_row;
                int ncol = warp_n * 32 + p * 16 + a_chk;
                ldsm_x4_t(r, &Bs[buf][krow][ncol]);
                bf[p * 2][0] = r[0]; bf[p * 2][1] = r[1];
                bf[p * 2 + 1][0] = r[2]; bf[p * 2 + 1][1] = r[3];
            }
            #pragma unroll
            for (int mi = 0; mi < 4; mi++)
                #pragma unroll
                for (int ni = 0; ni < 4; ni++)
                    mma_f16(acc[mi][ni], af[mi], bf[ni]);
        }
    }

    float* Cp = (float*)C;
    if (EPI == 3) Cp = (float*)C + (size_t)blockIdx.z * M * N;

    #pragma unroll
    for (int mi = 0; mi < 4; mi++) {
        const int row0 = by * 128 + warp_m * 64 + mi * 16 + g;
        #pragma unroll
        for (int ni = 0; ni < 4; ni++) {
            const int col = bx * 128 + warp_n * 32 + (ni >> 1) * 16 + (ni & 1) * 8 + 2 * t;
            #pragma unroll
            for (int half_ = 0; half_ < 2; half_++) {
                const int r = row0 + half_ * 8;
                if (EPI == 3) {
                    *(float2*)(Cp + (size_t)r * N + col) =
                        make_float2(acc[mi][ni][half_ * 2], acc[mi][ni][half_ * 2 + 1]);
                    continue;
                }
                float v0 = acc[mi][ni][half_ * 2]     + bias[col];
                float v1 = acc[mi][ni][half_ * 2 + 1] + bias[col + 1];
                if (EPI == 1) {
                    v0 = 0.5f * v0 * (1.f + erff(v0 * 0.70710678118654752f));
                    v1 = 0.5f * v1 * (1.f + erff(v1 * 0.70710678118654752f));
                } else if (EPI == 2) {
                    float2 rr = *(const float2*)(resid + (size_t)r * N + col);
                    v0 += rr.x; v1 += rr.y;
                }
                if (sizeof(CT) == 2) {
                    *(uint32_t*)((__half*)C + (size_t)r * N + col) = h2pack(v0, v1);
                } else {
                    *(float2*)((float*)C + (size_t)r * N + col) = make_float2(v0, v1);
                }
            }
        }
    }
}

// ---------------- RoPE on K slice only, 4 dims/thread ----------------
__global__ void rope_k_kernel(__half* __restrict__ qkv,
                              const float* __restrict__ cosp,
                              const float* __restrict__ sinp) {
    int idx = blockIdx.x * blockDim.x + threadIdx.x;  // S*H*8
    if (idx >= S_LEN * H_NUM * 8) return;
    const int d4 = (idx & 7) * 4;
    const int h = (idx >> 3) & (H_NUM - 1);
    const int s = idx >> 7;

    const float4 c1 = *(const float4*)(cosp + s * 64 + d4);
    const float4 c2 = *(const float4*)(cosp + s * 64 + d4 + 32);
    const float4 s1 = *(const float4*)(sinp + s * 64 + d4);
    const float4 s2 = *(const float4*)(sinp + s * 64 + d4 + 32);

    __half* p = qkv + (size_t)s * (3 * D_DIM) + D_DIM + h * HD_DIM + d4;
    __half2 a0 = *(__half2*)p,        a1 = *(__half2*)(p + 2);
    __half2 b0 = *(__half2*)(p + 32), b1 = *(__half2*)(p + 34);
    float2 af0 = __half22float2(a0), af1 = __half22float2(a1);
    float2 bf0 = __half22float2(b0), bf1 = __half22float2(b1);
    uint2 lo, hi;
    lo.x = h2pack(af0.x * c1.x - bf0.x * s1.x, af0.y * c1.y - bf0.y * s1.y);
    lo.y = h2pack(af1.x * c1.z - bf1.x * s1.z, af1.y * c1.w - bf1.y * s1.w);
    hi.x = h2pack(bf0.x * c2.x + af0.x * s2.x, bf0.y * c2.y + af0.y * s2.y);
    hi.y = h2pack(bf1.x * c2.z + af1.x * s2.z, bf1.y * c2.w + af1.y * s2.w);
    *(uint2*)p = lo;
    *(uint2*)(p + 32) = hi;
}

// ---- fp16 flash attention, 64-key double-buffered chunks; Q-RoPE+scale fused ----
__global__ __launch_bounds__(256)
void attn_kernel(const __half* __restrict__ qkv,
                 const int* __restrict__ cu,
                 const float* __restrict__ cosp,
                 const float* __restrict__ sinp,
                 __half* __restrict__ ao) {
    const int h  = blockIdx.y;
    const int s0 = blockIdx.x * 128;
    const int tid  = threadIdx.x;
    const int lane = tid & 31;
    const int wid  = tid >> 5;
    const int g = lane >> 2;
    const int t = lane & 3;
    const int a_row = lane & 15;
    const int a_chk = (lane >> 4) * 8;

    __shared__ __half Kh[2][64][72];
    __shared__ __half Vh[2][64][72];

    int start = 0, len = S_LEN;
    #pragma unroll
    for (int i = 0; i < NSEG; i++) {
        int a = cu[i], b = cu[i + 1];
        if (s0 >= a && s0 < b) { start = a; len = b - a; }
    }

    const int pr = wid * 16;

    // Q frags with fused RoPE and 1/8 scale
    uint32_t qf[4][4];
    {
        const int r0 = s0 + pr + g;
        const __half* q0 = qkv + (size_t)r0 * (3 * D_DIM) + h * HD_DIM;
        const __half* q8 = q0 + 8 * (3 * D_DIM);
        float2 raw[4][4];
        #pragma unroll
        for (int dc = 0; dc < 4; dc++) {
            const int c = dc * 16 + 2 * t;
            raw[dc][0] = __half22float2(*(const __half2*)(q0 + c));
            raw[dc][1] = __half22float2(*(const __half2*)(q8 + c));
            raw[dc][2] = __half22float2(*(const __half2*)(q0 + c + 8));
            raw[dc][3] = __half22float2(*(const __half2*)(q8 + c + 8));
        }
        #pragma unroll
        for (int dc = 0; dc < 4; dc++) {
            const float sgn = (dc < 2) ? -0.125f : 0.125f;
            #pragma unroll
            for (int j = 0; j < 4; j++) {
                const int row = (j & 1) ? (r0 + 8) : r0;
                const int d = dc * 16 + 2 * t + ((j >> 1) ? 8 : 0);
                float2 cv = *(const float2*)(cosp + row * 64 + d);
                float2 sv = *(const float2*)(sinp + row * 64 + d);
                float2 pp = raw[dc ^ 2][j];
                qf[dc][j] = h2pack(raw[dc][j].x * cv.x * 0.125f + sgn * pp.x * sv.x,
                                   raw[dc][j].y * cv.y * 0.125f + sgn * pp.y * sv.y);
            }
        }
    }

    float m0 = -3.4e38f, m1 = -3.4e38f, l0 = 0.f, l1 = 0.f;
    float out[8][4];
    #pragma unroll
    for (int n = 0; n < 8; n++)
        #pragma unroll
        for (int e = 0; e < 4; e++) out[n][e] = 0.f;

    const int kr = tid >> 3;         // 0..31
    const int kc8 = (tid & 7) * 8;
    auto load_chunk = [&](int buf, int kb) {
        #pragma unroll
        for (int rr = 0; rr < 2; rr++) {
            const __half* base = qkv + (size_t)(kb + kr + rr * 32) * (3 * D_DIM)
                               + h * HD_DIM + kc8;
            cp16(&Kh[buf][kr + rr * 32][kc8], base + D_DIM);
            cp16(&Vh[buf][kr + rr * 32][kc8], base + 2 * D_DIM);
        }
        cp_commit();
    };

    load_chunk(0, start);

    const int nch = len >> 6;       // 64-key chunks
    for (int c = 0; c < nch; c++) {
        const int buf = c & 1;
        asm volatile("cp.async.wait_group 0;\n");
        __syncthreads();
        if (c + 1 < nch) load_chunk(buf ^ 1, start + (c + 1) * 64);

        // S = Q @ K^T  (64 keys, scale pre-folded into Q)
        float sacc[8][4];
        #pragma unroll
        for (int j = 0; j < 8; j++)
            #pragma unroll
            for (int e = 0; e < 4; e++) sacc[j][e] = 0.f;
        #pragma unroll
        for (int dc = 0; dc < 4; dc++) {
            #pragma unroll
            for (int kh = 0; kh < 4; kh++) {
                uint32_t r[4];
                ldsm_x4(r, &Kh[buf][kh * 16 + a_row][dc * 16 + a_chk]);
                mma_f16_2(sacc[kh * 2],     qf[dc][0], qf[dc][1], qf[dc][2], qf[dc][3],
                          r[0], r[2]);
                mma_f16_2(sacc[kh * 2 + 1], qf[dc][0], qf[dc][1], qf[dc][2], qf[dc][3],
                          r[1], r[3]);
            }
        }

        // online softmax
        float ml0 = -3.4e38f, ml1 = -3.4e38f;
        #pragma unroll
        for (int j = 0; j < 8; j++) {
            ml0 = fmaxf(ml0, fmaxf(sacc[j][0], sacc[j][1]));
            ml1 = fmaxf(ml1, fmaxf(sacc[j][2], sacc[j][3]));
        }
        ml0 = fmaxf(ml0, __shfl_xor_sync(0xffffffffu, ml0, 1));
        ml0 = fmaxf(ml0, __shfl_xor_sync(0xffffffffu, ml0, 2));
        ml1 = fmaxf(ml1, __shfl_xor_sync(0xffffffffu, ml1, 1));
        ml1 = fmaxf(ml1, __shfl_xor_sync(0xffffffffu, ml1, 2));
        const float mn0 = fmaxf(m0, ml0);
        const float mn1 = fmaxf(m1, ml1);
        const float f0 = __expf(m0 - mn0);
        const float f1 = __expf(m1 - mn1);

        uint32_t pa[4][4];
        float ll0 = 0.f, ll1 = 0.f;
        #pragma unroll
        for (int j = 0; j < 8; j++) {
            float p0 = __expf(sacc[j][0] - mn0);
            float p1 = __expf(sacc[j][1] - mn0);
            float p2 = __expf(sacc[j][2] - mn1);
            float p3 = __expf(sacc[j][3] - mn1);
            ll0 += p0 + p1; ll1 += p2 + p3;
            pa[j >> 1][(j & 1) * 2]     = h2pack(p0, p1);
            pa[j >> 1][(j & 1) * 2 + 1] = h2pack(p2, p3);
        }
        ll0 += __shfl_xor_sync(0xffffffffu, ll0, 1);
        ll0 += __shfl_xor_sync(0xffffffffu, ll0, 2);
        ll1 += __shfl_xor_sync(0xffffffffu, ll1, 1);
        ll1 += __shfl_xor_sync(0xffffffffu, ll1, 2);
        l0 = l0 * f0 + ll0;
        l1 = l1 * f1 + ll1;
        m0 = mn0; m1 = mn1;
        #pragma unroll
        for (int n = 0; n < 8; n++) {
            out[n][0] *= f0; out[n][1] *= f0;
            out[n][2] *= f1; out[n][3] *= f1;
        }

        // out += P @ V
        #pragma unroll
        for (int kc = 0; kc < 4; kc++) {
            #pragma unroll
            for (int p = 0; p < 4; p++) {
                uint32_t r[4];
                ldsm_x4_t(r, &Vh[buf][kc * 16 + a_row][p * 16 + a_chk]);
                mma_f16(out[p * 2], pa[kc], r);
                mma_f16_2(out[p * 2 + 1], pa[kc][0], pa[kc][1], pa[kc][2], pa[kc][3],
                          r[2], r[3]);
            }
        }
    }

    const float i0 = 1.f / l0;
    const float i1 = 1.f / l1;
    __half* o0 = ao + (size_t)(s0 + pr + g) * D_DIM + h * HD_DIM;
    __half* o8 = o0 + 8 * D_DIM;
    #pragma unroll
    for (int n = 0; n < 8; n++) {
        *(uint32_t*)(o0 + 8 * n + 2 * t) = h2pack(out[n][0] * i0, out[n][1] * i0);
        *(uint32_t*)(o8 + 8 * n + 2 * t) = h2pack(out[n][2] * i1, out[n][3] * i1);
    }
}

// ---------------- driver ----------------
extern "C" void kernel_launch(void* const* d_in, const int* in_sizes, int n_in,
                              void* d_out, int out_size) {
    const float* hidden = (const float*)d_in[0];
    const int*   cu     = (const int*)d_in[1];
    const float* cosp   = (const float*)d_in[2];
    const float* sinp   = (const float*)d_in[3];
    const float* ln1_g  = (const float*)d_in[4];
    const float* ln1_b  = (const float*)d_in[5];
    const float* qkv_w  = (const float*)d_in[6];
    const float* qkv_b  = (const float*)d_in[7];
    const float* proj_w = (const float*)d_in[8];
    const float* proj_b = (const float*)d_in[9];
    const float* ln2_g  = (const float*)d_in[10];
    const float* ln2_b  = (const float*)d_in[11];
    const float* fc1_w  = (const float*)d_in[12];
    const float* fc1_b  = (const float*)d_in[13];
    const float* fc2_w  = (const float*)d_in[14];
    const float* fc2_b  = (const float*)d_in[15];

    float* x = (float*)d_out;

    __half *h, *qkv, *ao, *ff, *wq, *wp, *w1, *w2;
    float *part;
    cudaGetSymbolAddress((void**)&h,    g_h);
    cudaGetSymbolAddress((void**)&qkv,  g_qkv);
    cudaGetSymbolAddress((void**)&ao,   g_ao);
    cudaGetSymbolAddress((void**)&ff,   g_ff);
    cudaGetSymbolAddress((void**)&part, g_part);
    cudaGetSymbolAddress((void**)&wq,   g_wq);
    cudaGetSymbolAddress((void**)&wp,   g_wp);
    cudaGetSymbolAddress((void**)&w1,   g_w1);
    cudaGetSymbolAddress((void**)&w2,   g_w2);

    cudaFuncSetAttribute(gemm_f16_kernel<0, __half>,
                         cudaFuncAttributeMaxDynamicSharedMemorySize, G3_SMEM_BYTES);
    cudaFuncSetAttribute(gemm_f16_kernel<1, __half>,
                         cudaFuncAttributeMaxDynamicSharedMemorySize, G3_SMEM_BYTES);
    cudaFuncSetAttribute(gemm_f16_kernel<3, float>,
                         cudaFuncAttributeMaxDynamicSharedMemorySize, G3_SMEM_BYTES);

    // fused weight conversion (fp32 -> fp16), 16 elems/thread
    {
        const int n0 = DEPTH * D_DIM * 3 * D_DIM / 16;
        const int n1 = DEPTH * D_DIM * D_DIM / 16;
        const int n2 = DEPTH * D_DIM * FF_DIM / 16;
        const int n3 = DEPTH * FF_DIM * D_DIM / 16;
        const int total = n0 + n1 + n2 + n3;
        f2h_all_kernel<<<(total + 255) / 256, 256>>>(
            qkv_w, wq, n0, proj_w, wp, n1, fc1_w, w1, n2, fc2_w, w2, n3);
    }

    // x = hidden; h = LN1(hidden)   (fused copy + LN)
    copy_ln_kernel<<<S_LEN / 8, 256>>>(hidden, ln1_g, ln1_b, x, h);

    for (int i = 0; i < DEPTH; i++) {
        const __half* wqi = wq + (size_t)i * D_DIM * 3 * D_DIM;
        const float*  qb  = qkv_b  + (size_t)i * 3 * D_DIM;
        const __half* wpi = wp + (size_t)i * D_DIM * D_DIM;
        const float*  pb  = proj_b + (size_t)i * D_DIM;
        const __half* w1i = w1 + (size_t)i * D_DIM * FF_DIM;
        const float*  f1b = fc1_b  + (size_t)i * FF_DIM;
        const __half* w2i = w2 + (size_t)i * FF_DIM * D_DIM;
        const float*  f2b = fc2_b  + (size_t)i * D_DIM;

        {   // qkv = h @ qkv_w + qkv_b  (half out)
            dim3 grid(3 * D_DIM / 128, S_LEN / 128);
            gemm_f16_kernel<0, __half><<<grid, 256, G3_SMEM_BYTES>>>(
                h, wqi, qb, nullptr, qkv, S_LEN, 3 * D_DIM, D_DIM, D_DIM);
        }

        {   // RoPE on K only (Q fused into attention)
            int total = S_LEN * H_NUM * 8;
            rope_k_kernel<<<(total + 255) / 256, 256>>>(qkv, cosp, sinp);
        }

        {   // attention -> half ao
            dim3 grid(S_LEN / 128, H_NUM);
            attn_kernel<<<grid, 256>>>(qkv, cu, cosp, sinp, ao);
        }

        {   // proj: split-K2 partials, then fused reduce + LN2
            dim3 grid(D_DIM / 128, S_LEN / 128, 2);
            gemm_f16_kernel<3, float><<<grid, 256, G3_SMEM_BYTES>>>(
                ao, wpi, nullptr, nullptr, part, S_LEN, D_DIM, D_DIM / 2, D_DIM);
            red_ln_kernel<1><<<S_LEN / 8, 256>>>(part, pb, x, x,
                                                 ln2_g + (size_t)i * D_DIM,
                                                 ln2_b + (size_t)i * D_DIM, h);
        }

        {   // ff = gelu(h @ fc1_w + fc1_b)  (half out)
            dim3 grid(FF_DIM / 128, S_LEN / 128);
            gemm_f16_kernel<1, __half><<<grid, 256, G3_SMEM_BYTES>>>(
                h, w1i, f1b, nullptr, ff, S_LEN, FF_DIM, D_DIM, D_DIM);
        }

        {   // fc2: split-K2 partials, then reduce (+ fused next-layer LN1)
            dim3 grid(D_DIM / 128, S_LEN / 128, 2);
            gemm_f16_kernel<3, float><<<grid, 256, G3_SMEM_BYTES>>>(
                ff, w2i, nullptr, nullptr, part, S_LEN, D_DIM, FF_DIM / 2, FF_DIM);
            if (i + 1 < DEPTH) {
                red_ln_kernel<1><<<S_LEN / 8, 256>>>(part, f2b, x, x,
                                                     ln1_g + (size_t)(i + 1) * D_DIM,
                                                     ln1_b + (size_t)(i + 1) * D_DIM, h);
            } else {
                red_ln_kernel<0><<<S_LEN / 8, 256>>>(part, f2b, x, x,
                                                     nullptr, nullptr, nullptr);
            }
        }
    }
}